// round 4
// baseline (speedup 1.0000x reference)
#include <cuda_runtime.h>
#include <cuda_bf16.h>
#include <math.h>
#include <stdint.h>

// Problem dims (fixed)
#define BSZ   4096
#define KDIM  1024
#define K3B   3072      // 3 * KDIM bytes (int8 split-GEMM concatenated K)
#define N4    4096      // 4*H
#define HDIM  1024

// ---------------------------------------------------------------------------
// Device scratch (static, no dynamic allocation)
// ---------------------------------------------------------------------------
__device__ float g_gi[(size_t)BSZ * N4];   // input  @ w_i2h + b_i2h
__device__ float g_gh[(size_t)BSZ * N4];   // h_prev @ w_h2h + b_h2h

// int8 split operands. K layout (bytes):
//   A3[r] = [A1 | A0 | A0],  W3[n] = [W0 | W1 | W0]   (W transposed to [N,K])
// seg0: A1*W0 (scale sA*sW/256), seg1: A0*W1 (/256), seg2: A0*W0 (unit)
__device__ int8_t g_a3[2][(size_t)BSZ * K3B];
__device__ int8_t g_w3[2][(size_t)N4 * K3B];
__device__ float  g_sa[2][BSZ];       // per-row scale of A
__device__ float  g_sw[2][N4];        // per-col scale of W
__device__ float  g_swinv[2][N4];     // 127 / colmax
__device__ float  g_swpart[2][8][N4]; // partial col maxima

// ---------------------------------------------------------------------------
// Base-PTX helpers (legal on compute_103 virtual arch)
// ---------------------------------------------------------------------------
__device__ __forceinline__ uint32_t smem_u32(const void* p) {
    uint32_t a;
    asm("{ .reg .u64 t; cvta.to.shared.u64 t, %1; cvt.u32.u64 %0, t; }" : "=r"(a) : "l"(p));
    return a;
}
__device__ __forceinline__ void cp_async16(uint32_t s, const void* g) {
    asm volatile("cp.async.cg.shared.global [%0], [%1], 16;" :: "r"(s), "l"(g));
}
#define CP_COMMIT() asm volatile("cp.async.commit_group;" ::: "memory")
#define CP_WAIT(n)  asm volatile("cp.async.wait_group %0;" :: "n"(n) : "memory")

__device__ __forceinline__ void ldsm4(uint32_t& r0, uint32_t& r1, uint32_t& r2, uint32_t& r3,
                                      uint32_t addr) {
    asm volatile("ldmatrix.sync.aligned.m8n8.x4.shared.b16 {%0,%1,%2,%3}, [%4];"
                 : "=r"(r0), "=r"(r1), "=r"(r2), "=r"(r3) : "r"(addr));
}
__device__ __forceinline__ void mma_s8(int* c, const uint32_t* a, const uint32_t* b) {
    asm volatile(
        "mma.sync.aligned.m16n8k32.row.col.s32.s8.s8.s32 "
        "{%0,%1,%2,%3}, {%4,%5,%6,%7}, {%8,%9}, {%0,%1,%2,%3};"
        : "+r"(c[0]), "+r"(c[1]), "+r"(c[2]), "+r"(c[3])
        : "r"(a[0]), "r"(a[1]), "r"(a[2]), "r"(a[3]), "r"(b[0]), "r"(b[1]));
}

// ---------------------------------------------------------------------------
// Quantization kernels
// ---------------------------------------------------------------------------
__device__ __forceinline__ float block_reduce_max(float v)
{
    __shared__ float sbuf[8];
    const int lane = threadIdx.x & 31;
    const int warp = threadIdx.x >> 5;
    #pragma unroll
    for (int o = 16; o > 0; o >>= 1)
        v = fmaxf(v, __shfl_down_sync(0xffffffffu, v, o));
    if (lane == 0) sbuf[warp] = v;
    __syncthreads();
    if (warp == 0) {
        v = (lane < 8) ? sbuf[lane] : 0.0f;
        #pragma unroll
        for (int o = 4; o > 0; o >>= 1)
            v = fmaxf(v, __shfl_down_sync(0xffffffffu, v, o));
        if (lane == 0) sbuf[0] = v;
    }
    __syncthreads();
    float r = sbuf[0];
    __syncthreads();
    return r;
}

__device__ __forceinline__ int8_t q7(float x) {
    float r = rintf(x);
    r = fminf(fmaxf(r, -127.0f), 127.0f);
    return (int8_t)(int)r;
}

// Activations: one block per (row, plane). A row [1024] fp32 -> A3 row [3072] int8.
__global__ void __launch_bounds__(256) quant_act_kernel(
    const float* __restrict__ src0, const float* __restrict__ src1)
{
    const int plane = blockIdx.z;
    const int row = blockIdx.x;
    const float* __restrict__ src = (plane ? src1 : src0) + (size_t)row * KDIM;
    int8_t* __restrict__ dst = g_a3[plane] + (size_t)row * K3B;

    const int k = threadIdx.x * 4;
    float4 v = *(const float4*)(src + k);
    float m = fmaxf(fmaxf(fabsf(v.x), fabsf(v.y)), fmaxf(fabsf(v.z), fabsf(v.w)));
    m = block_reduce_max(m);

    const float inv = (m > 0.0f) ? 127.0f / m : 0.0f;
    if (threadIdx.x == 0) g_sa[plane][row] = m / 127.0f;

    float a[4] = {v.x * inv, v.y * inv, v.z * inv, v.w * inv};
    char4 c0, c1;
    int8_t* p0 = (int8_t*)&c0;   // A0
    int8_t* p1 = (int8_t*)&c1;   // A1
    #pragma unroll
    for (int i = 0; i < 4; i++) {
        float a0 = rintf(a[i]);
        a0 = fminf(fmaxf(a0, -127.0f), 127.0f);
        p0[i] = (int8_t)(int)a0;
        p1[i] = q7((a[i] - a0) * 256.0f);
    }
    *(char4*)(dst + k)            = c1;   // seg0: A1
    *(char4*)(dst + KDIM + k)     = c0;   // seg1: A0
    *(char4*)(dst + 2 * KDIM + k) = c0;   // seg2: A0
}

// W column maxima, stage 1: partial maxima over 128-row chunks
__global__ void __launch_bounds__(256) colmax_part_kernel(
    const float* __restrict__ w0, const float* __restrict__ w1)
{
    const int plane = blockIdx.z;
    const float* __restrict__ W = plane ? w1 : w0;
    const int n  = blockIdx.x * 256 + threadIdx.x;
    const int kc = blockIdx.y;
    float m = 0.0f;
    #pragma unroll 4
    for (int k = kc * 128; k < (kc + 1) * 128; k++)
        m = fmaxf(m, fabsf(W[(size_t)k * N4 + n]));
    g_swpart[plane][kc][n] = m;
}

// stage 2: finalize sW, swinv
__global__ void __launch_bounds__(256) colmax_fin_kernel()
{
    const int plane = blockIdx.z;
    const int n = blockIdx.x * 256 + threadIdx.x;
    float m = 0.0f;
    #pragma unroll
    for (int kc = 0; kc < 8; kc++) m = fmaxf(m, g_swpart[plane][kc][n]);
    g_sw[plane][n]    = m / 127.0f;
    g_swinv[plane][n] = (m > 0.0f) ? 127.0f / m : 0.0f;
}

// W [KDIM, N4] fp32 -> W3 [N4, 3072B] int8 (transpose + split)
__global__ void __launch_bounds__(256) quant_wt_kernel(
    const float* __restrict__ w0, const float* __restrict__ w1)
{
    const int plane = blockIdx.z;
    const float* __restrict__ W = plane ? w1 : w0;
    int8_t* __restrict__ D = g_w3[plane];

    __shared__ float tile[32][33];
    const int tx = threadIdx.x;          // 0..31
    const int ty = threadIdx.y;          // 0..7
    const int n0 = blockIdx.x * 32;      // N tile
    const int k0 = blockIdx.y * 32;      // K tile

    #pragma unroll
    for (int j = 0; j < 4; j++) {
        const int k = k0 + ty + j * 8;
        tile[ty + j * 8][tx] = W[(size_t)k * N4 + n0 + tx];
    }
    __syncthreads();
    #pragma unroll
    for (int j = 0; j < 4; j++) {
        const int n = n0 + ty + j * 8;
        const float inv = g_swinv[plane][n];
        const float v = tile[tx][ty + j * 8] * inv;   // = W[k0+tx][n] / sW
        float w0r = rintf(v);
        w0r = fminf(fmaxf(w0r, -127.0f), 127.0f);
        const int8_t W0 = (int8_t)(int)w0r;
        const int8_t W1 = q7((v - w0r) * 256.0f);
        int8_t* row = D + (size_t)n * K3B + k0 + tx;
        row[0]        = W0;   // seg0
        row[KDIM]     = W1;   // seg1
        row[2 * KDIM] = W0;   // seg2
    }
}

// ---------------------------------------------------------------------------
// int8 mma.sync GEMM: acc = A3 @ W3^T (segmented scales), C = sA*sW*acc + bias
// CTA tile 128x256, BK=64 bytes, 8 warps (2x4), warp tile 64x64, 3-stage cp.async
// ---------------------------------------------------------------------------
#define BM 128
#define BN 256
#define BKB 64
#define STAGES 3
#define A_ST ((BM) * (BKB))                 // 8192 B
#define B_ST ((BN) * (BKB))                 // 16384 B
#define STAGE_BYTES (A_ST + B_ST)           // 24576 B
#define GEMM_SMEM (STAGES * STAGE_BYTES)    // 73728 B
#define ITERS (K3B / BKB)                   // 48
#define SEG_HI 32                           // iter where unit-scale segment starts

// smem row = 64 bytes, 4 chunks of 16B; chunk' = chunk ^ ((r>>1)&3)
__device__ __forceinline__ uint32_t sw_off(int r, int chunk) {
    return (uint32_t)(r * 64 + ((chunk ^ ((r >> 1) & 3)) << 4));
}

__device__ __forceinline__ void load_stage(
    uint32_t sA, uint32_t sB,
    const int8_t* __restrict__ Ag, const int8_t* __restrict__ Wg,
    int m0, int n0, int kt, int tid)
{
    const int kbase = kt * BKB;
    #pragma unroll
    for (int i = 0; i < 2; i++) {                 // A: 512 16B-chunks / 256 thr
        const int id = tid + i * 256;
        const int r = id >> 2, kc = id & 3;
        cp_async16(sA + sw_off(r, kc), Ag + (size_t)(m0 + r) * K3B + kbase + kc * 16);
    }
    #pragma unroll
    for (int i = 0; i < 4; i++) {                 // B: 1024 chunks / 256 thr
        const int id = tid + i * 256;
        const int r = id >> 2, kc = id & 3;
        cp_async16(sB + sw_off(r, kc), Wg + (size_t)(n0 + r) * K3B + kbase + kc * 16);
    }
}

__global__ void __launch_bounds__(256, 1) gemm_imma_kernel(
    const float* __restrict__ bias0, const float* __restrict__ bias1)
{
    extern __shared__ char smem[];
    const uint32_t sbase = smem_u32(smem);
    const int tid  = threadIdx.x;
    const int lane = tid & 31;
    const int wid  = tid >> 5;
    const int wm   = wid >> 2;     // 0..1
    const int wn   = wid & 3;      // 0..3

    const int gemm = blockIdx.z;
    const int m0 = blockIdx.y * BM;
    const int n0 = blockIdx.x * BN;

    const int8_t* __restrict__ Ag = g_a3[gemm];
    const int8_t* __restrict__ Wg = g_w3[gemm];
    float* __restrict__ C = gemm ? g_gh : g_gi;
    const float* __restrict__ bias = gemm ? bias1 : bias0;
    const float* __restrict__ sa = g_sa[gemm];
    const float* __restrict__ sw = g_sw[gemm];

    int acc[4][8][4];
    #pragma unroll
    for (int i = 0; i < 4; i++)
        #pragma unroll
        for (int j = 0; j < 8; j++)
            #pragma unroll
            for (int r = 0; r < 4; r++)
                acc[i][j][r] = 0;

    const int row_a  = lane & 15;
    const int ksel_a = lane >> 4;
    const int row_b  = ((lane >> 4) << 3) | (lane & 7);
    const int ksel_b = (lane >> 3) & 1;

    load_stage(sbase, sbase + A_ST, Ag, Wg, m0, n0, 0, tid);
    CP_COMMIT();
    load_stage(sbase + STAGE_BYTES, sbase + STAGE_BYTES + A_ST, Ag, Wg, m0, n0, 1, tid);
    CP_COMMIT();

    #pragma unroll 1
    for (int kt = 0; kt < ITERS; kt++) {
        // rescale: lo segments (scale 1/256) finished -> shift into unit scale
        if (kt == SEG_HI) {
            #pragma unroll
            for (int i = 0; i < 4; i++)
                #pragma unroll
                for (int j = 0; j < 8; j++)
                    #pragma unroll
                    for (int r = 0; r < 4; r++)
                        acc[i][j][r] = (acc[i][j][r] + 128) >> 8;
        }

        CP_WAIT(1);
        __syncthreads();
        const int s = kt % STAGES;
        const uint32_t sA = sbase + s * STAGE_BYTES;
        const uint32_t sB = sA + A_ST;

        #pragma unroll
        for (int ks = 0; ks < 2; ks++) {
            uint32_t a[4][4], b[4][4];
            #pragma unroll
            for (int mt = 0; mt < 4; mt++) {
                const int r = wm * 64 + mt * 16 + row_a;
                ldsm4(a[mt][0], a[mt][1], a[mt][2], a[mt][3],
                      sA + sw_off(r, ks * 2 + ksel_a));
            }
            #pragma unroll
            for (int bt = 0; bt < 4; bt++) {
                const int n = wn * 64 + bt * 16 + row_b;
                ldsm4(b[bt][0], b[bt][1], b[bt][2], b[bt][3],
                      sB + sw_off(n, ks * 2 + ksel_b));
            }
            #pragma unroll
            for (int mt = 0; mt < 4; mt++)
                #pragma unroll
                for (int bt = 0; bt < 4; bt++) {
                    mma_s8(acc[mt][bt * 2],     a[mt], &b[bt][0]);
                    mma_s8(acc[mt][bt * 2 + 1], a[mt], &b[bt][2]);
                }
        }

        if (kt + 2 < ITERS) {
            const int sn = (kt + 2) % STAGES;
            load_stage(sbase + sn * STAGE_BYTES, sbase + sn * STAGE_BYTES + A_ST,
                       Ag, Wg, m0, n0, kt + 2, tid);
        }
        CP_COMMIT();
    }

    // epilogue: C = sA[m]*sW[n]*acc + bias[n]
    float2 swv[8], bv[8];
    #pragma unroll
    for (int nf = 0; nf < 8; nf++) {
        const int n = n0 + wn * 64 + nf * 8 + (lane & 3) * 2;
        swv[nf] = *(const float2*)(sw + n);
        bv[nf]  = *(const float2*)(bias + n);
    }
    #pragma unroll
    for (int mt = 0; mt < 4; mt++) {
        const int m = m0 + wm * 64 + mt * 16 + (lane >> 2);
        const float sa0 = sa[m];
        const float sa1 = sa[m + 8];
        #pragma unroll
        for (int nf = 0; nf < 8; nf++) {
            const int n = n0 + wn * 64 + nf * 8 + (lane & 3) * 2;
            float2 o0, o1;
            o0.x = (float)acc[mt][nf][0] * (sa0 * swv[nf].x) + bv[nf].x;
            o0.y = (float)acc[mt][nf][1] * (sa0 * swv[nf].y) + bv[nf].y;
            o1.x = (float)acc[mt][nf][2] * (sa1 * swv[nf].x) + bv[nf].x;
            o1.y = (float)acc[mt][nf][3] * (sa1 * swv[nf].y) + bv[nf].y;
            *(float2*)&C[(size_t)m * N4 + n]       = o0;
            *(float2*)&C[(size_t)(m + 8) * N4 + n] = o1;
        }
    }
}

// ---------------------------------------------------------------------------
// Fused LayerNorm + LSTM gate kernel (unchanged)
// ---------------------------------------------------------------------------
__device__ __forceinline__ float4 block_reduce_sum4(float4 v)
{
    __shared__ float4 sbuf[8];
    const int lane = threadIdx.x & 31;
    const int warp = threadIdx.x >> 5;
    #pragma unroll
    for (int o = 16; o > 0; o >>= 1) {
        v.x += __shfl_down_sync(0xffffffffu, v.x, o);
        v.y += __shfl_down_sync(0xffffffffu, v.y, o);
        v.z += __shfl_down_sync(0xffffffffu, v.z, o);
        v.w += __shfl_down_sync(0xffffffffu, v.w, o);
    }
    if (lane == 0) sbuf[warp] = v;
    __syncthreads();
    if (warp == 0) {
        v = (lane < 8) ? sbuf[lane] : make_float4(0.f, 0.f, 0.f, 0.f);
        #pragma unroll
        for (int o = 4; o > 0; o >>= 1) {
            v.x += __shfl_down_sync(0xffffffffu, v.x, o);
            v.y += __shfl_down_sync(0xffffffffu, v.y, o);
            v.z += __shfl_down_sync(0xffffffffu, v.z, o);
            v.w += __shfl_down_sync(0xffffffffu, v.w, o);
        }
        if (lane == 0) sbuf[0] = v;
    }
    __syncthreads();
    float4 res = sbuf[0];
    __syncthreads();
    return res;
}

__device__ __forceinline__ float sigmoidf_(float x) { return 1.0f / (1.0f + expf(-x)); }

__global__ void __launch_bounds__(256) ln_lstm_kernel(
    const float* __restrict__ c_prev,
    const float* __restrict__ g_i2h,  const float* __restrict__ be_i2h,
    const float* __restrict__ g_h2h,  const float* __restrict__ be_h2h,
    const float* __restrict__ g_c,    const float* __restrict__ be_c,
    float* __restrict__ out_h, float* __restrict__ out_c)
{
    const int row = blockIdx.x;
    const int t   = threadIdx.x;
    const float* gi = g_gi + (size_t)row * N4;
    const float* gh = g_gh + (size_t)row * N4;

    float vi[16], vh[16];
    float4 s = make_float4(0.f, 0.f, 0.f, 0.f);
    #pragma unroll
    for (int k = 0; k < 16; k++) {
        const int idx = t + k * 256;
        vi[k] = gi[idx];
        vh[k] = gh[idx];
        s.x += vi[k]; s.y += vi[k] * vi[k];
        s.z += vh[k]; s.w += vh[k] * vh[k];
    }
    s = block_reduce_sum4(s);

    const float n1  = (float)N4;
    const float mi  = s.x / n1;
    const float mh  = s.z / n1;
    const float var_i = (s.y - n1 * mi * mi) / (n1 - 1.0f);
    const float var_h = (s.w - n1 * mh * mh) / (n1 - 1.0f);
    const float inv_i = 1.0f / (sqrtf(fmaxf(var_i, 0.f)) + 1e-6f);
    const float inv_h = 1.0f / (sqrtf(fmaxf(var_h, 0.f)) + 1e-6f);

    float sg[16];
    #pragma unroll
    for (int k = 0; k < 16; k++) {
        const int idx = t + k * 256;
        const float ni = g_i2h[idx] * (vi[k] - mi) * inv_i + be_i2h[idx];
        const float nh = g_h2h[idx] * (vh[k] - mh) * inv_h + be_h2h[idx];
        sg[k] = ni + nh;
    }

    float cn[4], og[4];
    float4 cs = make_float4(0.f, 0.f, 0.f, 0.f);
    #pragma unroll
    for (int k = 0; k < 4; k++) {
        const int j = t + k * 256;
        const float ig = sg[k];
        const float fg = sg[k + 4];
        const float ug = sg[k + 8];
        og[k]          = sg[k + 12];
        const float cp = c_prev[(size_t)row * HDIM + j];
        cn[k] = cp * sigmoidf_(fg + 1.0f) + tanhf(ug) * sigmoidf_(ig);
        cs.x += cn[k];
        cs.y += cn[k] * cn[k];
    }
    cs = block_reduce_sum4(cs);

    const float n2   = (float)HDIM;
    const float mc   = cs.x / n2;
    const float var_c = (cs.y - n2 * mc * mc) / (n2 - 1.0f);
    const float inv_c = 1.0f / (sqrtf(fmaxf(var_c, 0.f)) + 1e-6f);

    #pragma unroll
    for (int k = 0; k < 4; k++) {
        const int j = t + k * 256;
        const float cval = g_c[j] * (cn[k] - mc) * inv_c + be_c[j];
        out_c[(size_t)row * HDIM + j] = cval;
        out_h[(size_t)row * HDIM + j] = sigmoidf_(og[k]) * tanhf(cval);
    }
}

// ---------------------------------------------------------------------------
extern "C" void kernel_launch(void* const* d_in, const int* in_sizes, int n_in,
                              void* d_out, int out_size)
{
    const float* input  = (const float*)d_in[0];
    const float* h_prev = (const float*)d_in[1];
    const float* c_prev = (const float*)d_in[2];
    const float* w_i2h  = (const float*)d_in[3];
    const float* b_i2h  = (const float*)d_in[4];
    const float* w_h2h  = (const float*)d_in[5];
    const float* b_h2h  = (const float*)d_in[6];
    const float* gi2h   = (const float*)d_in[7];
    const float* bei2h  = (const float*)d_in[8];
    const float* gh2h   = (const float*)d_in[9];
    const float* beh2h  = (const float*)d_in[10];
    const float* gc     = (const float*)d_in[11];
    const float* bec    = (const float*)d_in[12];

    float* out_h = (float*)d_out;
    float* out_c = (float*)d_out + (size_t)BSZ * HDIM;

    // quantization
    quant_act_kernel<<<dim3(BSZ, 1, 2), 256>>>(input, h_prev);
    colmax_part_kernel<<<dim3(N4 / 256, 8, 2), 256>>>(w_i2h, w_h2h);
    colmax_fin_kernel<<<dim3(N4 / 256, 1, 2), 256>>>();
    quant_wt_kernel<<<dim3(N4 / 32, KDIM / 32, 2), dim3(32, 8)>>>(w_i2h, w_h2h);

    // int8 tensor-core GEMMs
    cudaFuncSetAttribute(gemm_imma_kernel,
                         cudaFuncAttributeMaxDynamicSharedMemorySize, GEMM_SMEM);
    gemm_imma_kernel<<<dim3(N4 / BN, BSZ / BM, 2), 256, GEMM_SMEM>>>(b_i2h, b_h2h);

    ln_lstm_kernel<<<BSZ, 256>>>(c_prev, gi2h, bei2h, gh2h, beh2h, gc, bec,
                                 out_h, out_c);
}

// round 5
// speedup vs baseline: 3.4324x; 3.4324x over previous
#include <cuda_runtime.h>
#include <cuda_fp16.h>
#include <math.h>
#include <stdint.h>

// Problem dims (fixed)
#define BSZ   4096
#define KDIM  1024
#define K2    2048      // 2 * KDIM (fp16 split-GEMM concatenated K)
#define N4    4096      // 4*H
#define HDIM  1024

// ---------------------------------------------------------------------------
// Device scratch (static, no dynamic allocation)
// ---------------------------------------------------------------------------
__device__ float g_gi[(size_t)BSZ * N4];   // input  @ w_i2h + b_i2h
__device__ float g_gh[(size_t)BSZ * N4];   // h_prev @ w_h2h + b_h2h

// fp16 split operands:
//   A2[r][0:1024]=A_hi, [1024:2048]=A_lo      (A = A_hi + A_lo exactly)
//   W2[n][0:1024]=W_hi, [1024:2048]=W_hi      (W transposed to [N,K])
// => A2 @ W2^T over K=2048 == (A_hi + A_lo) @ W_hi == A @ W_hi  (fp32 accum)
__device__ __half g_a2[2][(size_t)BSZ * K2];
__device__ __half g_w2[2][(size_t)N4 * K2];

// ---------------------------------------------------------------------------
// Base-PTX helpers (legal on compute_103 virtual arch)
// ---------------------------------------------------------------------------
__device__ __forceinline__ uint32_t smem_u32(const void* p) {
    uint32_t a;
    asm("{ .reg .u64 t; cvta.to.shared.u64 t, %1; cvt.u32.u64 %0, t; }" : "=r"(a) : "l"(p));
    return a;
}
__device__ __forceinline__ void cp_async16(uint32_t s, const void* g) {
    asm volatile("cp.async.cg.shared.global [%0], [%1], 16;" :: "r"(s), "l"(g));
}
#define CP_COMMIT() asm volatile("cp.async.commit_group;" ::: "memory")
#define CP_WAIT(n)  asm volatile("cp.async.wait_group %0;" :: "n"(n) : "memory")

__device__ __forceinline__ void ldsm4(uint32_t& r0, uint32_t& r1, uint32_t& r2, uint32_t& r3,
                                      uint32_t addr) {
    asm volatile("ldmatrix.sync.aligned.m8n8.x4.shared.b16 {%0,%1,%2,%3}, [%4];"
                 : "=r"(r0), "=r"(r1), "=r"(r2), "=r"(r3) : "r"(addr));
}
__device__ __forceinline__ void mma_f16(float* c, const uint32_t* a, const uint32_t* b) {
    asm volatile(
        "mma.sync.aligned.m16n8k16.row.col.f32.f16.f16.f32 "
        "{%0,%1,%2,%3}, {%4,%5,%6,%7}, {%8,%9}, {%0,%1,%2,%3};"
        : "+f"(c[0]), "+f"(c[1]), "+f"(c[2]), "+f"(c[3])
        : "r"(a[0]), "r"(a[1]), "r"(a[2]), "r"(a[3]), "r"(b[0]), "r"(b[1]));
}

// ---------------------------------------------------------------------------
// Conversion kernels
// ---------------------------------------------------------------------------
// Activations: one row per block. src row [1024] fp32 -> A2 row [2048] fp16.
__global__ void __launch_bounds__(256) split_act_kernel(
    const float* __restrict__ src0, const float* __restrict__ src1)
{
    const int plane = blockIdx.z;
    const float* __restrict__ src = plane ? src1 : src0;
    __half* __restrict__ dst = g_a2[plane] + (size_t)blockIdx.x * K2;

    const int k = threadIdx.x * 4;
    float4 v = *(const float4*)(src + (size_t)blockIdx.x * KDIM + k);

    __half h0 = __float2half(v.x), h1 = __float2half(v.y);
    __half h2 = __float2half(v.z), h3 = __float2half(v.w);
    float l0 = v.x - __half2float(h0), l1 = v.y - __half2float(h1);
    float l2 = v.z - __half2float(h2), l3 = v.w - __half2float(h3);

    union { __half2 h2v[2]; uint2 u; } ph, pl;
    ph.h2v[0] = __halves2half2(h0, h1);
    ph.h2v[1] = __halves2half2(h2, h3);
    pl.h2v[0] = __floats2half2_rn(l0, l1);
    pl.h2v[1] = __floats2half2_rn(l2, l3);

    *(uint2*)(dst + k)        = ph.u;   // seg0: hi
    *(uint2*)(dst + KDIM + k) = pl.u;   // seg1: lo
}

// Weights: W [KDIM, N4] fp32 -> W2 [N4, 2048] fp16 (transpose, hi duplicated)
__global__ void __launch_bounds__(256) split_wt_kernel(
    const float* __restrict__ w0, const float* __restrict__ w1)
{
    const int plane = blockIdx.z;
    const float* __restrict__ W = plane ? w1 : w0;
    __half* __restrict__ D = g_w2[plane];

    __shared__ float tile[32][33];
    const int tx = threadIdx.x;          // 0..31
    const int ty = threadIdx.y;          // 0..7
    const int n0 = blockIdx.x * 32;      // N tile
    const int k0 = blockIdx.y * 32;      // K tile

    #pragma unroll
    for (int j = 0; j < 4; j++) {
        const int k = k0 + ty + j * 8;
        tile[ty + j * 8][tx] = W[(size_t)k * N4 + n0 + tx];
    }
    __syncthreads();
    #pragma unroll
    for (int j = 0; j < 4; j++) {
        const int n = n0 + ty + j * 8;
        const __half h = __float2half(tile[tx][ty + j * 8]);   // = W[k0+tx][n]
        __half* row = D + (size_t)n * K2 + k0 + tx;
        row[0]    = h;       // seg0: hi
        row[KDIM] = h;       // seg1: hi (paired with A_lo)
    }
}

// ---------------------------------------------------------------------------
// fp16 mma.sync GEMM: C[4096, 4096] = A2[4096,2048] @ W2[4096,2048]^T + bias
// CTA tile 128x256, BK=32, 8 warps (2x4), warp tile 64x64, 3-stage cp.async.
// ---------------------------------------------------------------------------
#define BM 128
#define BN 256
#define BK 32
#define STAGES 3
#define A_ST ((BM) * (BK) * 2)                  // 8192 B
#define B_ST ((BN) * (BK) * 2)                  // 16384 B
#define STAGE_BYTES (A_ST + B_ST)               // 24576 B
#define GEMM_SMEM (STAGES * STAGE_BYTES)        // 73728 B
#define ITERS (K2 / BK)                         // 64

// smem element [r][k] (k in 0..31 fp16): 4 chunks of 16B per 64B row,
// chunk' = chunk ^ ((r>>1)&3) — conflict-free for ldmatrix 8-row phases.
__device__ __forceinline__ uint32_t sw_off(int r, int chunk) {
    return (uint32_t)(r * 64 + ((chunk ^ ((r >> 1) & 3)) << 4));
}

__device__ __forceinline__ void load_stage(
    uint32_t sA, uint32_t sB,
    const __half* __restrict__ Ag, const __half* __restrict__ Wg,
    int m0, int n0, int kt, int tid)
{
    const int kbase = kt * BK;
    #pragma unroll
    for (int i = 0; i < 2; i++) {                 // A: 512 chunks / 256 thr
        const int id = tid + i * 256;
        const int r = id >> 2, kc = id & 3;
        cp_async16(sA + sw_off(r, kc), Ag + (size_t)(m0 + r) * K2 + kbase + kc * 8);
    }
    #pragma unroll
    for (int i = 0; i < 4; i++) {                 // B: 1024 chunks / 256 thr
        const int id = tid + i * 256;
        const int r = id >> 2, kc = id & 3;
        cp_async16(sB + sw_off(r, kc), Wg + (size_t)(n0 + r) * K2 + kbase + kc * 8);
    }
}

__global__ void __launch_bounds__(256, 1) gemm_mma_kernel(
    const float* __restrict__ bias0, const float* __restrict__ bias1)
{
    extern __shared__ char smem[];
    const uint32_t sbase = smem_u32(smem);
    const int tid  = threadIdx.x;
    const int lane = tid & 31;
    const int wid  = tid >> 5;
    const int wm   = wid >> 2;     // 0..1 -> m offset 64*wm
    const int wn   = wid & 3;      // 0..3 -> n offset 64*wn

    const int gemm = blockIdx.z;
    const int m0 = blockIdx.y * BM;
    const int n0 = blockIdx.x * BN;

    const __half* __restrict__ Ag = g_a2[gemm];
    const __half* __restrict__ Wg = g_w2[gemm];
    float* __restrict__ C = gemm ? g_gh : g_gi;
    const float* __restrict__ bias = gemm ? bias1 : bias0;

    float acc[4][8][4];
    #pragma unroll
    for (int i = 0; i < 4; i++)
        #pragma unroll
        for (int j = 0; j < 8; j++)
            #pragma unroll
            for (int r = 0; r < 4; r++)
                acc[i][j][r] = 0.0f;

    // ldmatrix per-lane addressing components
    const int row_a  = lane & 15;
    const int ksel_a = lane >> 4;
    const int row_b  = ((lane >> 4) << 3) | (lane & 7);
    const int ksel_b = (lane >> 3) & 1;

    load_stage(sbase, sbase + A_ST, Ag, Wg, m0, n0, 0, tid);
    CP_COMMIT();
    load_stage(sbase + STAGE_BYTES, sbase + STAGE_BYTES + A_ST, Ag, Wg, m0, n0, 1, tid);
    CP_COMMIT();

    #pragma unroll 1
    for (int kt = 0; kt < ITERS; kt++) {
        CP_WAIT(1);
        __syncthreads();
        const int s = kt % STAGES;
        const uint32_t sA = sbase + s * STAGE_BYTES;
        const uint32_t sB = sA + A_ST;

        #pragma unroll
        for (int ks = 0; ks < 2; ks++) {
            uint32_t a[4][4], b[4][4];
            #pragma unroll
            for (int mt = 0; mt < 4; mt++) {
                const int r = wm * 64 + mt * 16 + row_a;
                ldsm4(a[mt][0], a[mt][1], a[mt][2], a[mt][3],
                      sA + sw_off(r, ks * 2 + ksel_a));
            }
            #pragma unroll
            for (int bt = 0; bt < 4; bt++) {
                const int n = wn * 64 + bt * 16 + row_b;
                ldsm4(b[bt][0], b[bt][1], b[bt][2], b[bt][3],
                      sB + sw_off(n, ks * 2 + ksel_b));
            }
            #pragma unroll
            for (int mt = 0; mt < 4; mt++)
                #pragma unroll
                for (int bt = 0; bt < 4; bt++) {
                    mma_f16(acc[mt][bt * 2],     a[mt], &b[bt][0]);
                    mma_f16(acc[mt][bt * 2 + 1], a[mt], &b[bt][2]);
                }
        }

        if (kt + 2 < ITERS) {
            const int sn = (kt + 2) % STAGES;
            load_stage(sbase + sn * STAGE_BYTES, sbase + sn * STAGE_BYTES + A_ST,
                       Ag, Wg, m0, n0, kt + 2, tid);
        }
        CP_COMMIT();
    }

    // epilogue: bias add + store fp32
    float2 bv[8];
    #pragma unroll
    for (int nf = 0; nf < 8; nf++) {
        const int n = n0 + wn * 64 + nf * 8 + (lane & 3) * 2;
        bv[nf] = *(const float2*)(bias + n);
    }
    #pragma unroll
    for (int mt = 0; mt < 4; mt++) {
        const int m = m0 + wm * 64 + mt * 16 + (lane >> 2);
        #pragma unroll
        for (int nf = 0; nf < 8; nf++) {
            const int n = n0 + wn * 64 + nf * 8 + (lane & 3) * 2;
            float2 o0, o1;
            o0.x = acc[mt][nf][0] + bv[nf].x;
            o0.y = acc[mt][nf][1] + bv[nf].y;
            o1.x = acc[mt][nf][2] + bv[nf].x;
            o1.y = acc[mt][nf][3] + bv[nf].y;
            *(float2*)&C[(size_t)m * N4 + n]       = o0;
            *(float2*)&C[(size_t)(m + 8) * N4 + n] = o1;
        }
    }
}

// ---------------------------------------------------------------------------
// Fused LayerNorm + LSTM gate kernel (unchanged from passing baseline)
// ---------------------------------------------------------------------------
__device__ __forceinline__ float4 block_reduce_sum4(float4 v)
{
    __shared__ float4 sbuf[8];
    const int lane = threadIdx.x & 31;
    const int warp = threadIdx.x >> 5;
    #pragma unroll
    for (int o = 16; o > 0; o >>= 1) {
        v.x += __shfl_down_sync(0xffffffffu, v.x, o);
        v.y += __shfl_down_sync(0xffffffffu, v.y, o);
        v.z += __shfl_down_sync(0xffffffffu, v.z, o);
        v.w += __shfl_down_sync(0xffffffffu, v.w, o);
    }
    if (lane == 0) sbuf[warp] = v;
    __syncthreads();
    if (warp == 0) {
        v = (lane < 8) ? sbuf[lane] : make_float4(0.f, 0.f, 0.f, 0.f);
        #pragma unroll
        for (int o = 4; o > 0; o >>= 1) {
            v.x += __shfl_down_sync(0xffffffffu, v.x, o);
            v.y += __shfl_down_sync(0xffffffffu, v.y, o);
            v.z += __shfl_down_sync(0xffffffffu, v.z, o);
            v.w += __shfl_down_sync(0xffffffffu, v.w, o);
        }
        if (lane == 0) sbuf[0] = v;
    }
    __syncthreads();
    float4 res = sbuf[0];
    __syncthreads();
    return res;
}

__device__ __forceinline__ float sigmoidf_(float x) { return 1.0f / (1.0f + expf(-x)); }

__global__ void __launch_bounds__(256) ln_lstm_kernel(
    const float* __restrict__ c_prev,
    const float* __restrict__ g_i2h,  const float* __restrict__ be_i2h,
    const float* __restrict__ g_h2h,  const float* __restrict__ be_h2h,
    const float* __restrict__ g_c,    const float* __restrict__ be_c,
    float* __restrict__ out_h, float* __restrict__ out_c)
{
    const int row = blockIdx.x;
    const int t   = threadIdx.x;
    const float* gi = g_gi + (size_t)row * N4;
    const float* gh = g_gh + (size_t)row * N4;

    float vi[16], vh[16];
    float4 s = make_float4(0.f, 0.f, 0.f, 0.f);
    #pragma unroll
    for (int k = 0; k < 16; k++) {
        const int idx = t + k * 256;
        vi[k] = gi[idx];
        vh[k] = gh[idx];
        s.x += vi[k]; s.y += vi[k] * vi[k];
        s.z += vh[k]; s.w += vh[k] * vh[k];
    }
    s = block_reduce_sum4(s);

    const float n1  = (float)N4;
    const float mi  = s.x / n1;
    const float mh  = s.z / n1;
    const float var_i = (s.y - n1 * mi * mi) / (n1 - 1.0f);
    const float var_h = (s.w - n1 * mh * mh) / (n1 - 1.0f);
    const float inv_i = 1.0f / (sqrtf(fmaxf(var_i, 0.f)) + 1e-6f);
    const float inv_h = 1.0f / (sqrtf(fmaxf(var_h, 0.f)) + 1e-6f);

    float sg[16];
    #pragma unroll
    for (int k = 0; k < 16; k++) {
        const int idx = t + k * 256;
        const float ni = g_i2h[idx] * (vi[k] - mi) * inv_i + be_i2h[idx];
        const float nh = g_h2h[idx] * (vh[k] - mh) * inv_h + be_h2h[idx];
        sg[k] = ni + nh;
    }

    float cn[4], og[4];
    float4 cs = make_float4(0.f, 0.f, 0.f, 0.f);
    #pragma unroll
    for (int k = 0; k < 4; k++) {
        const int j = t + k * 256;
        const float ig = sg[k];
        const float fg = sg[k + 4];
        const float ug = sg[k + 8];
        og[k]          = sg[k + 12];
        const float cp = c_prev[(size_t)row * HDIM + j];
        cn[k] = cp * sigmoidf_(fg + 1.0f) + tanhf(ug) * sigmoidf_(ig);
        cs.x += cn[k];
        cs.y += cn[k] * cn[k];
    }
    cs = block_reduce_sum4(cs);

    const float n2   = (float)HDIM;
    const float mc   = cs.x / n2;
    const float var_c = (cs.y - n2 * mc * mc) / (n2 - 1.0f);
    const float inv_c = 1.0f / (sqrtf(fmaxf(var_c, 0.f)) + 1e-6f);

    #pragma unroll
    for (int k = 0; k < 4; k++) {
        const int j = t + k * 256;
        const float cval = g_c[j] * (cn[k] - mc) * inv_c + be_c[j];
        out_c[(size_t)row * HDIM + j] = cval;
        out_h[(size_t)row * HDIM + j] = sigmoidf_(og[k]) * tanhf(cval);
    }
}

// ---------------------------------------------------------------------------
extern "C" void kernel_launch(void* const* d_in, const int* in_sizes, int n_in,
                              void* d_out, int out_size)
{
    const float* input  = (const float*)d_in[0];
    const float* h_prev = (const float*)d_in[1];
    const float* c_prev = (const float*)d_in[2];
    const float* w_i2h  = (const float*)d_in[3];
    const float* b_i2h  = (const float*)d_in[4];
    const float* w_h2h  = (const float*)d_in[5];
    const float* b_h2h  = (const float*)d_in[6];
    const float* gi2h   = (const float*)d_in[7];
    const float* bei2h  = (const float*)d_in[8];
    const float* gh2h   = (const float*)d_in[9];
    const float* beh2h  = (const float*)d_in[10];
    const float* gc     = (const float*)d_in[11];
    const float* bec    = (const float*)d_in[12];

    float* out_h = (float*)d_out;
    float* out_c = (float*)d_out + (size_t)BSZ * HDIM;

    // conversions: build A2 / W2 fp16 split operands
    split_act_kernel<<<dim3(BSZ, 1, 2), 256>>>(input, h_prev);
    split_wt_kernel<<<dim3(N4 / 32, KDIM / 32, 2), dim3(32, 8)>>>(w_i2h, w_h2h);

    // GEMMs on tensor pipe (mma.sync fp16)
    cudaFuncSetAttribute(gemm_mma_kernel,
                         cudaFuncAttributeMaxDynamicSharedMemorySize, GEMM_SMEM);
    gemm_mma_kernel<<<dim3(N4 / BN, BSZ / BM, 2), 256, GEMM_SMEM>>>(b_i2h, b_h2h);

    ln_lstm_kernel<<<BSZ, 256>>>(c_prev, gi2h, bei2h, gh2h, beh2h, gc, bec,
                                 out_h, out_c);
}

// round 6
// speedup vs baseline: 3.9045x; 1.1375x over previous
#include <cuda_runtime.h>
#include <cuda_fp16.h>
#include <math.h>
#include <stdint.h>

// Problem dims (fixed)
#define BSZ   4096
#define KDIM  1024
#define N4    4096   // 4*H
#define HDIM  1024

// ---------------------------------------------------------------------------
// Device scratch (static, no dynamic allocation)
// ---------------------------------------------------------------------------
__device__ float g_gi[(size_t)BSZ * N4];   // input  @ w_i2h + b_i2h
__device__ float g_gh[(size_t)BSZ * N4];   // h_prev @ w_h2h + b_h2h

// fp16 operands: A [BSZ, KDIM], W transposed [N4, KDIM]
__device__ __half g_a2[2][(size_t)BSZ * KDIM];
__device__ __half g_w2[2][(size_t)N4 * KDIM];

// ---------------------------------------------------------------------------
// Base-PTX helpers (legal on compute_103 virtual arch)
// ---------------------------------------------------------------------------
__device__ __forceinline__ uint32_t smem_u32(const void* p) {
    uint32_t a;
    asm("{ .reg .u64 t; cvta.to.shared.u64 t, %1; cvt.u32.u64 %0, t; }" : "=r"(a) : "l"(p));
    return a;
}
__device__ __forceinline__ void cp_async16(uint32_t s, const void* g) {
    asm volatile("cp.async.cg.shared.global [%0], [%1], 16;" :: "r"(s), "l"(g));
}
#define CP_COMMIT() asm volatile("cp.async.commit_group;" ::: "memory")
#define CP_WAIT(n)  asm volatile("cp.async.wait_group %0;" :: "n"(n) : "memory")

__device__ __forceinline__ void ldsm4(uint32_t& r0, uint32_t& r1, uint32_t& r2, uint32_t& r3,
                                      uint32_t addr) {
    asm volatile("ldmatrix.sync.aligned.m8n8.x4.shared.b16 {%0,%1,%2,%3}, [%4];"
                 : "=r"(r0), "=r"(r1), "=r"(r2), "=r"(r3) : "r"(addr));
}
__device__ __forceinline__ void mma_f16(float* c, const uint32_t* a, const uint32_t* b) {
    asm volatile(
        "mma.sync.aligned.m16n8k16.row.col.f32.f16.f16.f32 "
        "{%0,%1,%2,%3}, {%4,%5,%6,%7}, {%8,%9}, {%0,%1,%2,%3};"
        : "+f"(c[0]), "+f"(c[1]), "+f"(c[2]), "+f"(c[3])
        : "r"(a[0]), "r"(a[1]), "r"(a[2]), "r"(a[3]), "r"(b[0]), "r"(b[1]));
}

// ---------------------------------------------------------------------------
// Conversion kernels
// ---------------------------------------------------------------------------
// Activations: plain fp32 -> fp16 cast (grid-stride over both planes)
__global__ void __launch_bounds__(256) cast_act_kernel(
    const float* __restrict__ src0, const float* __restrict__ src1)
{
    const int plane = blockIdx.z;
    const float* __restrict__ src = plane ? src1 : src0;
    __half* __restrict__ dst = g_a2[plane];

    const size_t idx = ((size_t)blockIdx.x * 256 + threadIdx.x) * 4;
    float4 v = *(const float4*)(src + idx);
    union { __half2 h2v[2]; uint2 u; } p;
    p.h2v[0] = __floats2half2_rn(v.x, v.y);
    p.h2v[1] = __floats2half2_rn(v.z, v.w);
    *(uint2*)(dst + idx) = p.u;
}

// Weights: W [KDIM, N4] fp32 -> W2 [N4, KDIM] fp16 (transpose)
__global__ void __launch_bounds__(256) cast_wt_kernel(
    const float* __restrict__ w0, const float* __restrict__ w1)
{
    const int plane = blockIdx.z;
    const float* __restrict__ W = plane ? w1 : w0;
    __half* __restrict__ D = g_w2[plane];

    __shared__ float tile[32][33];
    const int tx = threadIdx.x;          // 0..31
    const int ty = threadIdx.y;          // 0..7
    const int n0 = blockIdx.x * 32;      // N tile
    const int k0 = blockIdx.y * 32;      // K tile

    #pragma unroll
    for (int j = 0; j < 4; j++) {
        const int k = k0 + ty + j * 8;
        tile[ty + j * 8][tx] = W[(size_t)k * N4 + n0 + tx];
    }
    __syncthreads();
    #pragma unroll
    for (int j = 0; j < 4; j++) {
        const int n = n0 + ty + j * 8;
        D[(size_t)n * KDIM + k0 + tx] = __float2half(tile[tx][ty + j * 8]);
    }
}

// ---------------------------------------------------------------------------
// fp16 mma.sync GEMM: C[4096, 4096] = A[4096,1024] @ W[4096,1024]^T + bias
// CTA tile 128x256, BK=32, 8 warps (2x4), warp tile 64x64, 3-stage cp.async.
// ---------------------------------------------------------------------------
#define BM 128
#define BN 256
#define BK 32
#define STAGES 3
#define A_ST ((BM) * (BK) * 2)                  // 8192 B
#define B_ST ((BN) * (BK) * 2)                  // 16384 B
#define STAGE_BYTES (A_ST + B_ST)               // 24576 B
#define GEMM_SMEM (STAGES * STAGE_BYTES)        // 73728 B
#define ITERS (KDIM / BK)                       // 32

// smem row = 64B (32 fp16), 4 chunks of 16B; chunk' = chunk ^ ((r>>1)&3)
__device__ __forceinline__ uint32_t sw_off(int r, int chunk) {
    return (uint32_t)(r * 64 + ((chunk ^ ((r >> 1) & 3)) << 4));
}

__device__ __forceinline__ void load_stage(
    uint32_t sA, uint32_t sB,
    const __half* __restrict__ Ag, const __half* __restrict__ Wg,
    int m0, int n0, int kt, int tid)
{
    const int kbase = kt * BK;
    #pragma unroll
    for (int i = 0; i < 2; i++) {                 // A: 512 chunks / 256 thr
        const int id = tid + i * 256;
        const int r = id >> 2, kc = id & 3;
        cp_async16(sA + sw_off(r, kc), Ag + (size_t)(m0 + r) * KDIM + kbase + kc * 8);
    }
    #pragma unroll
    for (int i = 0; i < 4; i++) {                 // B: 1024 chunks / 256 thr
        const int id = tid + i * 256;
        const int r = id >> 2, kc = id & 3;
        cp_async16(sB + sw_off(r, kc), Wg + (size_t)(n0 + r) * KDIM + kbase + kc * 8);
    }
}

__global__ void __launch_bounds__(256, 1) gemm_mma_kernel(
    const float* __restrict__ bias0, const float* __restrict__ bias1)
{
    extern __shared__ char smem[];
    const uint32_t sbase = smem_u32(smem);
    const int tid  = threadIdx.x;
    const int lane = tid & 31;
    const int wid  = tid >> 5;
    const int wm   = wid >> 2;     // 0..1
    const int wn   = wid & 3;      // 0..3

    const int gemm = blockIdx.z;
    const int m0 = blockIdx.y * BM;
    const int n0 = blockIdx.x * BN;

    const __half* __restrict__ Ag = g_a2[gemm];
    const __half* __restrict__ Wg = g_w2[gemm];
    float* __restrict__ C = gemm ? g_gh : g_gi;
    const float* __restrict__ bias = gemm ? bias1 : bias0;

    float acc[4][8][4];
    #pragma unroll
    for (int i = 0; i < 4; i++)
        #pragma unroll
        for (int j = 0; j < 8; j++)
            #pragma unroll
            for (int r = 0; r < 4; r++)
                acc[i][j][r] = 0.0f;

    const int row_a  = lane & 15;
    const int ksel_a = lane >> 4;
    const int row_b  = ((lane >> 4) << 3) | (lane & 7);
    const int ksel_b = (lane >> 3) & 1;

    load_stage(sbase, sbase + A_ST, Ag, Wg, m0, n0, 0, tid);
    CP_COMMIT();
    load_stage(sbase + STAGE_BYTES, sbase + STAGE_BYTES + A_ST, Ag, Wg, m0, n0, 1, tid);
    CP_COMMIT();

    #pragma unroll 1
    for (int kt = 0; kt < ITERS; kt++) {
        CP_WAIT(1);
        __syncthreads();
        const int s = kt % STAGES;
        const uint32_t sA = sbase + s * STAGE_BYTES;
        const uint32_t sB = sA + A_ST;

        #pragma unroll
        for (int ks = 0; ks < 2; ks++) {
            uint32_t a[4][4], b[4][4];
            #pragma unroll
            for (int mt = 0; mt < 4; mt++) {
                const int r = wm * 64 + mt * 16 + row_a;
                ldsm4(a[mt][0], a[mt][1], a[mt][2], a[mt][3],
                      sA + sw_off(r, ks * 2 + ksel_a));
            }
            #pragma unroll
            for (int bt = 0; bt < 4; bt++) {
                const int n = wn * 64 + bt * 16 + row_b;
                ldsm4(b[bt][0], b[bt][1], b[bt][2], b[bt][3],
                      sB + sw_off(n, ks * 2 + ksel_b));
            }
            #pragma unroll
            for (int mt = 0; mt < 4; mt++)
                #pragma unroll
                for (int bt = 0; bt < 4; bt++) {
                    mma_f16(acc[mt][bt * 2],     a[mt], &b[bt][0]);
                    mma_f16(acc[mt][bt * 2 + 1], a[mt], &b[bt][2]);
                }
        }

        if (kt + 2 < ITERS) {
            const int sn = (kt + 2) % STAGES;
            load_stage(sbase + sn * STAGE_BYTES, sbase + sn * STAGE_BYTES + A_ST,
                       Ag, Wg, m0, n0, kt + 2, tid);
        }
        CP_COMMIT();
    }

    // epilogue: bias add + store fp32
    float2 bv[8];
    #pragma unroll
    for (int nf = 0; nf < 8; nf++) {
        const int n = n0 + wn * 64 + nf * 8 + (lane & 3) * 2;
        bv[nf] = *(const float2*)(bias + n);
    }
    #pragma unroll
    for (int mt = 0; mt < 4; mt++) {
        const int m = m0 + wm * 64 + mt * 16 + (lane >> 2);
        #pragma unroll
        for (int nf = 0; nf < 8; nf++) {
            const int n = n0 + wn * 64 + nf * 8 + (lane & 3) * 2;
            float2 o0, o1;
            o0.x = acc[mt][nf][0] + bv[nf].x;
            o0.y = acc[mt][nf][1] + bv[nf].y;
            o1.x = acc[mt][nf][2] + bv[nf].x;
            o1.y = acc[mt][nf][3] + bv[nf].y;
            *(float2*)&C[(size_t)m * N4 + n]       = o0;
            *(float2*)&C[(size_t)(m + 8) * N4 + n] = o1;
        }
    }
}

// ---------------------------------------------------------------------------
// Fused LayerNorm + LSTM gates, fully float4-vectorized.
// One block (256 threads) per batch row; thread t owns columns 4t..4t+3 of
// each of the 4 gate segments (idx = g*1024 + 4t + x) -> all gates of a given
// column j live in one thread; every global access is a coalesced float4.
// ---------------------------------------------------------------------------
__device__ __forceinline__ float4 block_reduce_sum4(float4 v)
{
    __shared__ float4 sbuf[8];
    const int lane = threadIdx.x & 31;
    const int warp = threadIdx.x >> 5;
    #pragma unroll
    for (int o = 16; o > 0; o >>= 1) {
        v.x += __shfl_down_sync(0xffffffffu, v.x, o);
        v.y += __shfl_down_sync(0xffffffffu, v.y, o);
        v.z += __shfl_down_sync(0xffffffffu, v.z, o);
        v.w += __shfl_down_sync(0xffffffffu, v.w, o);
    }
    if (lane == 0) sbuf[warp] = v;
    __syncthreads();
    if (warp == 0) {
        v = (lane < 8) ? sbuf[lane] : make_float4(0.f, 0.f, 0.f, 0.f);
        #pragma unroll
        for (int o = 4; o > 0; o >>= 1) {
            v.x += __shfl_down_sync(0xffffffffu, v.x, o);
            v.y += __shfl_down_sync(0xffffffffu, v.y, o);
            v.z += __shfl_down_sync(0xffffffffu, v.z, o);
            v.w += __shfl_down_sync(0xffffffffu, v.w, o);
        }
        if (lane == 0) sbuf[0] = v;
    }
    __syncthreads();
    float4 res = sbuf[0];
    __syncthreads();
    return res;
}

__device__ __forceinline__ float sigmoidf_(float x) { return 1.0f / (1.0f + expf(-x)); }

__global__ void __launch_bounds__(256) ln_lstm_kernel(
    const float* __restrict__ c_prev,
    const float* __restrict__ g_i2h,  const float* __restrict__ be_i2h,
    const float* __restrict__ g_h2h,  const float* __restrict__ be_h2h,
    const float* __restrict__ g_c,    const float* __restrict__ be_c,
    float* __restrict__ out_h, float* __restrict__ out_c)
{
    const int row = blockIdx.x;
    const int t   = threadIdx.x;
    const int c4  = t * 4;                         // column base within gate
    const float* gi = g_gi + (size_t)row * N4;
    const float* gh = g_gh + (size_t)row * N4;

    float4 vi[4], vh[4];
    float4 s = make_float4(0.f, 0.f, 0.f, 0.f);    // sum_i, sumsq_i, sum_h, sumsq_h
    #pragma unroll
    for (int g = 0; g < 4; g++) {
        vi[g] = *(const float4*)(gi + g * 1024 + c4);
        vh[g] = *(const float4*)(gh + g * 1024 + c4);
        s.x += vi[g].x + vi[g].y + vi[g].z + vi[g].w;
        s.y += vi[g].x * vi[g].x + vi[g].y * vi[g].y + vi[g].z * vi[g].z + vi[g].w * vi[g].w;
        s.z += vh[g].x + vh[g].y + vh[g].z + vh[g].w;
        s.w += vh[g].x * vh[g].x + vh[g].y * vh[g].y + vh[g].z * vh[g].z + vh[g].w * vh[g].w;
    }
    s = block_reduce_sum4(s);

    const float n1  = (float)N4;
    const float mi  = s.x / n1;
    const float mh  = s.z / n1;
    const float var_i = (s.y - n1 * mi * mi) / (n1 - 1.0f);
    const float var_h = (s.w - n1 * mh * mh) / (n1 - 1.0f);
    const float inv_i = 1.0f / (sqrtf(fmaxf(var_i, 0.f)) + 1e-6f);
    const float inv_h = 1.0f / (sqrtf(fmaxf(var_h, 0.f)) + 1e-6f);

    // normalized sum per gate: sg[g] covers columns c4..c4+3
    float sg[4][4];
    #pragma unroll
    for (int g = 0; g < 4; g++) {
        const int idx = g * 1024 + c4;
        const float4 ga = *(const float4*)(g_i2h + idx);
        const float4 ba = *(const float4*)(be_i2h + idx);
        const float4 gb = *(const float4*)(g_h2h + idx);
        const float4 bb = *(const float4*)(be_h2h + idx);
        sg[g][0] = ga.x * (vi[g].x - mi) * inv_i + ba.x + gb.x * (vh[g].x - mh) * inv_h + bb.x;
        sg[g][1] = ga.y * (vi[g].y - mi) * inv_i + ba.y + gb.y * (vh[g].y - mh) * inv_h + bb.y;
        sg[g][2] = ga.z * (vi[g].z - mi) * inv_i + ba.z + gb.z * (vh[g].z - mh) * inv_h + bb.z;
        sg[g][3] = ga.w * (vi[g].w - mi) * inv_i + ba.w + gb.w * (vh[g].w - mh) * inv_h + bb.w;
    }

    // gates: i=sg[0], f=sg[1], u=sg[2], o=sg[3]
    const float4 cp = *(const float4*)(c_prev + (size_t)row * HDIM + c4);
    float cn[4];
    float4 cs = make_float4(0.f, 0.f, 0.f, 0.f);
    const float cpv[4] = {cp.x, cp.y, cp.z, cp.w};
    #pragma unroll
    for (int x = 0; x < 4; x++) {
        cn[x] = cpv[x] * sigmoidf_(sg[1][x] + 1.0f) + tanhf(sg[2][x]) * sigmoidf_(sg[0][x]);
        cs.x += cn[x];
        cs.y += cn[x] * cn[x];
    }
    cs = block_reduce_sum4(cs);

    const float n2   = (float)HDIM;
    const float mc   = cs.x / n2;
    const float var_c = (cs.y - n2 * mc * mc) / (n2 - 1.0f);
    const float inv_c = 1.0f / (sqrtf(fmaxf(var_c, 0.f)) + 1e-6f);

    const float4 gcv  = *(const float4*)(g_c + c4);
    const float4 becv = *(const float4*)(be_c + c4);
    const float gca[4]  = {gcv.x, gcv.y, gcv.z, gcv.w};
    const float beca[4] = {becv.x, becv.y, becv.z, becv.w};

    float4 oc, oh;
    float* ocp = &oc.x;
    float* ohp = &oh.x;
    #pragma unroll
    for (int x = 0; x < 4; x++) {
        const float cval = gca[x] * (cn[x] - mc) * inv_c + beca[x];
        ocp[x] = cval;
        ohp[x] = sigmoidf_(sg[3][x]) * tanhf(cval);
    }
    *(float4*)(out_c + (size_t)row * HDIM + c4) = oc;
    *(float4*)(out_h + (size_t)row * HDIM + c4) = oh;
}

// ---------------------------------------------------------------------------
extern "C" void kernel_launch(void* const* d_in, const int* in_sizes, int n_in,
                              void* d_out, int out_size)
{
    const float* input  = (const float*)d_in[0];
    const float* h_prev = (const float*)d_in[1];
    const float* c_prev = (const float*)d_in[2];
    const float* w_i2h  = (const float*)d_in[3];
    const float* b_i2h  = (const float*)d_in[4];
    const float* w_h2h  = (const float*)d_in[5];
    const float* b_h2h  = (const float*)d_in[6];
    const float* gi2h   = (const float*)d_in[7];
    const float* bei2h  = (const float*)d_in[8];
    const float* gh2h   = (const float*)d_in[9];
    const float* beh2h  = (const float*)d_in[10];
    const float* gc     = (const float*)d_in[11];
    const float* bec    = (const float*)d_in[12];

    float* out_h = (float*)d_out;
    float* out_c = (float*)d_out + (size_t)BSZ * HDIM;

    // conversions
    cast_act_kernel<<<dim3(BSZ * KDIM / (256 * 4), 1, 2), 256>>>(input, h_prev);
    cast_wt_kernel<<<dim3(N4 / 32, KDIM / 32, 2), dim3(32, 8)>>>(w_i2h, w_h2h);

    // GEMMs on tensor pipe (mma.sync fp16, K=1024)
    cudaFuncSetAttribute(gemm_mma_kernel,
                         cudaFuncAttributeMaxDynamicSharedMemorySize, GEMM_SMEM);
    gemm_mma_kernel<<<dim3(N4 / BN, BSZ / BM, 2), 256, GEMM_SMEM>>>(b_i2h, b_h2h);

    ln_lstm_kernel<<<BSZ, 256>>>(c_prev, gi2h, bei2h, gh2h, beh2h, gc, bec,
                                 out_h, out_c);
}

// round 7
// speedup vs baseline: 5.5150x; 1.4125x over previous
#include <cuda_runtime.h>
#include <cuda_fp16.h>
#include <math.h>
#include <stdint.h>

// Problem dims (fixed)
#define BSZ   4096
#define KDIM  1024
#define N4    4096   // 4*H
#define HDIM  1024

// ---------------------------------------------------------------------------
// Device scratch (static, no dynamic allocation)
// ---------------------------------------------------------------------------
__device__ float g_gi[(size_t)BSZ * N4];   // input  @ w_i2h + b_i2h
__device__ float g_gh[(size_t)BSZ * N4];   // h_prev @ w_h2h + b_h2h

// fp16 operands: A [BSZ, KDIM], W transposed [N4, KDIM]
__device__ __half g_a2[2][(size_t)BSZ * KDIM];
__device__ __half g_w2[2][(size_t)N4 * KDIM];

// ---------------------------------------------------------------------------
// Base-PTX helpers (legal on compute_103 virtual arch)
// ---------------------------------------------------------------------------
__device__ __forceinline__ uint32_t smem_u32(const void* p) {
    uint32_t a;
    asm("{ .reg .u64 t; cvta.to.shared.u64 t, %1; cvt.u32.u64 %0, t; }" : "=r"(a) : "l"(p));
    return a;
}
__device__ __forceinline__ void cp_async16(uint32_t s, const void* g) {
    asm volatile("cp.async.cg.shared.global [%0], [%1], 16;" :: "r"(s), "l"(g));
}
#define CP_COMMIT() asm volatile("cp.async.commit_group;" ::: "memory")
#define CP_WAIT(n)  asm volatile("cp.async.wait_group %0;" :: "n"(n) : "memory")

__device__ __forceinline__ void ldsm4(uint32_t& r0, uint32_t& r1, uint32_t& r2, uint32_t& r3,
                                      uint32_t addr) {
    asm volatile("ldmatrix.sync.aligned.m8n8.x4.shared.b16 {%0,%1,%2,%3}, [%4];"
                 : "=r"(r0), "=r"(r1), "=r"(r2), "=r"(r3) : "r"(addr));
}
__device__ __forceinline__ void mma_f16(float* c, const uint32_t* a, const uint32_t* b) {
    asm volatile(
        "mma.sync.aligned.m16n8k16.row.col.f32.f16.f16.f32 "
        "{%0,%1,%2,%3}, {%4,%5,%6,%7}, {%8,%9}, {%0,%1,%2,%3};"
        : "+f"(c[0]), "+f"(c[1]), "+f"(c[2]), "+f"(c[3])
        : "r"(a[0]), "r"(a[1]), "r"(a[2]), "r"(a[3]), "r"(b[0]), "r"(b[1]));
}

// ---------------------------------------------------------------------------
// Conversion kernels
// ---------------------------------------------------------------------------
__global__ void __launch_bounds__(256) cast_act_kernel(
    const float* __restrict__ src0, const float* __restrict__ src1)
{
    const int plane = blockIdx.z;
    const float* __restrict__ src = plane ? src1 : src0;
    __half* __restrict__ dst = g_a2[plane];

    const size_t idx = ((size_t)blockIdx.x * 256 + threadIdx.x) * 4;
    float4 v = *(const float4*)(src + idx);
    union { __half2 h2v[2]; uint2 u; } p;
    p.h2v[0] = __floats2half2_rn(v.x, v.y);
    p.h2v[1] = __floats2half2_rn(v.z, v.w);
    *(uint2*)(dst + idx) = p.u;
}

// Weights: W [KDIM, N4] fp32 -> W2 [N4, KDIM] fp16 (transpose)
__global__ void __launch_bounds__(256) cast_wt_kernel(
    const float* __restrict__ w0, const float* __restrict__ w1)
{
    const int plane = blockIdx.z;
    const float* __restrict__ W = plane ? w1 : w0;
    __half* __restrict__ D = g_w2[plane];

    __shared__ float tile[32][33];
    const int tx = threadIdx.x;          // 0..31
    const int ty = threadIdx.y;          // 0..7
    const int n0 = blockIdx.x * 32;      // N tile
    const int k0 = blockIdx.y * 32;      // K tile

    #pragma unroll
    for (int j = 0; j < 4; j++) {
        const int k = k0 + ty + j * 8;
        tile[ty + j * 8][tx] = W[(size_t)k * N4 + n0 + tx];
    }
    __syncthreads();
    #pragma unroll
    for (int j = 0; j < 4; j++) {
        const int n = n0 + ty + j * 8;
        D[(size_t)n * KDIM + k0 + tx] = __float2half(tile[tx][ty + j * 8]);
    }
}

// ---------------------------------------------------------------------------
// fp16 mma.sync GEMM: C[4096, 4096] = A[4096,1024] @ W[4096,1024]^T + bias
// CTA tile 128x256, BK=32, 512 threads (16 warps, 4x4), warp tile 32x64,
// 3-stage cp.async pipeline. 4 warps/SMSP for latency hiding.
// ---------------------------------------------------------------------------
#define BM 128
#define BN 256
#define BK 32
#define STAGES 3
#define A_ST ((BM) * (BK) * 2)                  // 8192 B
#define B_ST ((BN) * (BK) * 2)                  // 16384 B
#define STAGE_BYTES (A_ST + B_ST)               // 24576 B
#define GEMM_SMEM (STAGES * STAGE_BYTES)        // 73728 B
#define ITERS (KDIM / BK)                       // 32

// smem row = 64B (32 fp16), 4 chunks of 16B; chunk' = chunk ^ ((r>>1)&3)
__device__ __forceinline__ uint32_t sw_off(int r, int chunk) {
    return (uint32_t)(r * 64 + ((chunk ^ ((r >> 1) & 3)) << 4));
}

__device__ __forceinline__ void load_stage(
    uint32_t sA, uint32_t sB,
    const __half* __restrict__ Ag, const __half* __restrict__ Wg,
    int m0, int n0, int kt, int tid)
{
    const int kbase = kt * BK;
    {                                             // A: 512 chunks / 512 thr
        const int r = tid >> 2, kc = tid & 3;
        cp_async16(sA + sw_off(r, kc), Ag + (size_t)(m0 + r) * KDIM + kbase + kc * 8);
    }
    #pragma unroll
    for (int i = 0; i < 2; i++) {                 // B: 1024 chunks / 512 thr
        const int id = tid + i * 512;
        const int r = id >> 2, kc = id & 3;
        cp_async16(sB + sw_off(r, kc), Wg + (size_t)(n0 + r) * KDIM + kbase + kc * 8);
    }
}

__global__ void __launch_bounds__(512, 1) gemm_mma_kernel(
    const float* __restrict__ bias0, const float* __restrict__ bias1)
{
    extern __shared__ char smem[];
    const uint32_t sbase = smem_u32(smem);
    const int tid  = threadIdx.x;
    const int lane = tid & 31;
    const int wid  = tid >> 5;
    const int wm   = wid >> 2;     // 0..3 -> m offset 32*wm
    const int wn   = wid & 3;      // 0..3 -> n offset 64*wn

    const int gemm = blockIdx.z;
    const int m0 = blockIdx.y * BM;
    const int n0 = blockIdx.x * BN;

    const __half* __restrict__ Ag = g_a2[gemm];
    const __half* __restrict__ Wg = g_w2[gemm];
    float* __restrict__ C = gemm ? g_gh : g_gi;
    const float* __restrict__ bias = gemm ? bias1 : bias0;

    float acc[2][8][4];
    #pragma unroll
    for (int i = 0; i < 2; i++)
        #pragma unroll
        for (int j = 0; j < 8; j++)
            #pragma unroll
            for (int r = 0; r < 4; r++)
                acc[i][j][r] = 0.0f;

    const int row_a  = lane & 15;
    const int ksel_a = lane >> 4;
    const int row_b  = ((lane >> 4) << 3) | (lane & 7);
    const int ksel_b = (lane >> 3) & 1;

    load_stage(sbase, sbase + A_ST, Ag, Wg, m0, n0, 0, tid);
    CP_COMMIT();
    load_stage(sbase + STAGE_BYTES, sbase + STAGE_BYTES + A_ST, Ag, Wg, m0, n0, 1, tid);
    CP_COMMIT();

    #pragma unroll 1
    for (int kt = 0; kt < ITERS; kt++) {
        CP_WAIT(1);
        __syncthreads();
        const int s = kt % STAGES;
        const uint32_t sA = sbase + s * STAGE_BYTES;
        const uint32_t sB = sA + A_ST;

        #pragma unroll
        for (int ks = 0; ks < 2; ks++) {
            uint32_t a[2][4], b[4][4];
            #pragma unroll
            for (int mt = 0; mt < 2; mt++) {
                const int r = wm * 32 + mt * 16 + row_a;
                ldsm4(a[mt][0], a[mt][1], a[mt][2], a[mt][3],
                      sA + sw_off(r, ks * 2 + ksel_a));
            }
            #pragma unroll
            for (int bt = 0; bt < 4; bt++) {
                const int n = wn * 64 + bt * 16 + row_b;
                ldsm4(b[bt][0], b[bt][1], b[bt][2], b[bt][3],
                      sB + sw_off(n, ks * 2 + ksel_b));
            }
            #pragma unroll
            for (int mt = 0; mt < 2; mt++)
                #pragma unroll
                for (int bt = 0; bt < 4; bt++) {
                    mma_f16(acc[mt][bt * 2],     a[mt], &b[bt][0]);
                    mma_f16(acc[mt][bt * 2 + 1], a[mt], &b[bt][2]);
                }
        }

        if (kt + 2 < ITERS) {
            const int sn = (kt + 2) % STAGES;
            load_stage(sbase + sn * STAGE_BYTES, sbase + sn * STAGE_BYTES + A_ST,
                       Ag, Wg, m0, n0, kt + 2, tid);
        }
        CP_COMMIT();
    }

    // epilogue: bias add + store fp32
    float2 bv[8];
    #pragma unroll
    for (int nf = 0; nf < 8; nf++) {
        const int n = n0 + wn * 64 + nf * 8 + (lane & 3) * 2;
        bv[nf] = *(const float2*)(bias + n);
    }
    #pragma unroll
    for (int mt = 0; mt < 2; mt++) {
        const int m = m0 + wm * 32 + mt * 16 + (lane >> 2);
        #pragma unroll
        for (int nf = 0; nf < 8; nf++) {
            const int n = n0 + wn * 64 + nf * 8 + (lane & 3) * 2;
            float2 o0, o1;
            o0.x = acc[mt][nf][0] + bv[nf].x;
            o0.y = acc[mt][nf][1] + bv[nf].y;
            o1.x = acc[mt][nf][2] + bv[nf].x;
            o1.y = acc[mt][nf][3] + bv[nf].y;
            *(float2*)&C[(size_t)m * N4 + n]       = o0;
            *(float2*)&C[(size_t)(m + 8) * N4 + n] = o1;
        }
    }
}

// ---------------------------------------------------------------------------
// Fused LayerNorm + LSTM gates (R5 layout: idx = t + k*256, measured 49 us)
// ---------------------------------------------------------------------------
__device__ __forceinline__ float4 block_reduce_sum4(float4 v)
{
    __shared__ float4 sbuf[8];
    const int lane = threadIdx.x & 31;
    const int warp = threadIdx.x >> 5;
    #pragma unroll
    for (int o = 16; o > 0; o >>= 1) {
        v.x += __shfl_down_sync(0xffffffffu, v.x, o);
        v.y += __shfl_down_sync(0xffffffffu, v.y, o);
        v.z += __shfl_down_sync(0xffffffffu, v.z, o);
        v.w += __shfl_down_sync(0xffffffffu, v.w, o);
    }
    if (lane == 0) sbuf[warp] = v;
    __syncthreads();
    if (warp == 0) {
        v = (lane < 8) ? sbuf[lane] : make_float4(0.f, 0.f, 0.f, 0.f);
        #pragma unroll
        for (int o = 4; o > 0; o >>= 1) {
            v.x += __shfl_down_sync(0xffffffffu, v.x, o);
            v.y += __shfl_down_sync(0xffffffffu, v.y, o);
            v.z += __shfl_down_sync(0xffffffffu, v.z, o);
            v.w += __shfl_down_sync(0xffffffffu, v.w, o);
        }
        if (lane == 0) sbuf[0] = v;
    }
    __syncthreads();
    float4 res = sbuf[0];
    __syncthreads();
    return res;
}

__device__ __forceinline__ float sigmoidf_(float x) { return 1.0f / (1.0f + expf(-x)); }

__global__ void __launch_bounds__(256) ln_lstm_kernel(
    const float* __restrict__ c_prev,
    const float* __restrict__ g_i2h,  const float* __restrict__ be_i2h,
    const float* __restrict__ g_h2h,  const float* __restrict__ be_h2h,
    const float* __restrict__ g_c,    const float* __restrict__ be_c,
    float* __restrict__ out_h, float* __restrict__ out_c)
{
    const int row = blockIdx.x;
    const int t   = threadIdx.x;
    const float* gi = g_gi + (size_t)row * N4;
    const float* gh = g_gh + (size_t)row * N4;

    float vi[16], vh[16];
    float4 s = make_float4(0.f, 0.f, 0.f, 0.f);
    #pragma unroll
    for (int k = 0; k < 16; k++) {
        const int idx = t + k * 256;
        vi[k] = gi[idx];
        vh[k] = gh[idx];
        s.x += vi[k]; s.y += vi[k] * vi[k];
        s.z += vh[k]; s.w += vh[k] * vh[k];
    }
    s = block_reduce_sum4(s);

    const float n1  = (float)N4;
    const float mi  = s.x / n1;
    const float mh  = s.z / n1;
    const float var_i = (s.y - n1 * mi * mi) / (n1 - 1.0f);
    const float var_h = (s.w - n1 * mh * mh) / (n1 - 1.0f);
    const float inv_i = 1.0f / (sqrtf(fmaxf(var_i, 0.f)) + 1e-6f);
    const float inv_h = 1.0f / (sqrtf(fmaxf(var_h, 0.f)) + 1e-6f);

    float sg[16];
    #pragma unroll
    for (int k = 0; k < 16; k++) {
        const int idx = t + k * 256;
        const float ni = g_i2h[idx] * (vi[k] - mi) * inv_i + be_i2h[idx];
        const float nh = g_h2h[idx] * (vh[k] - mh) * inv_h + be_h2h[idx];
        sg[k] = ni + nh;
    }

    float cn[4], og[4];
    float4 cs = make_float4(0.f, 0.f, 0.f, 0.f);
    #pragma unroll
    for (int k = 0; k < 4; k++) {
        const int j = t + k * 256;
        const float ig = sg[k];
        const float fg = sg[k + 4];
        const float ug = sg[k + 8];
        og[k]          = sg[k + 12];
        const float cp = c_prev[(size_t)row * HDIM + j];
        cn[k] = cp * sigmoidf_(fg + 1.0f) + tanhf(ug) * sigmoidf_(ig);
        cs.x += cn[k];
        cs.y += cn[k] * cn[k];
    }
    cs = block_reduce_sum4(cs);

    const float n2   = (float)HDIM;
    const float mc   = cs.x / n2;
    const float var_c = (cs.y - n2 * mc * mc) / (n2 - 1.0f);
    const float inv_c = 1.0f / (sqrtf(fmaxf(var_c, 0.f)) + 1e-6f);

    #pragma unroll
    for (int k = 0; k < 4; k++) {
        const int j = t + k * 256;
        const float cval = g_c[j] * (cn[k] - mc) * inv_c + be_c[j];
        out_c[(size_t)row * HDIM + j] = cval;
        out_h[(size_t)row * HDIM + j] = sigmoidf_(og[k]) * tanhf(cval);
    }
}

// ---------------------------------------------------------------------------
extern "C" void kernel_launch(void* const* d_in, const int* in_sizes, int n_in,
                              void* d_out, int out_size)
{
    const float* input  = (const float*)d_in[0];
    const float* h_prev = (const float*)d_in[1];
    const float* c_prev = (const float*)d_in[2];
    const float* w_i2h  = (const float*)d_in[3];
    const float* b_i2h  = (const float*)d_in[4];
    const float* w_h2h  = (const float*)d_in[5];
    const float* b_h2h  = (const float*)d_in[6];
    const float* gi2h   = (const float*)d_in[7];
    const float* bei2h  = (const float*)d_in[8];
    const float* gh2h   = (const float*)d_in[9];
    const float* beh2h  = (const float*)d_in[10];
    const float* gc     = (const float*)d_in[11];
    const float* bec    = (const float*)d_in[12];

    float* out_h = (float*)d_out;
    float* out_c = (float*)d_out + (size_t)BSZ * HDIM;

    // conversions
    cast_act_kernel<<<dim3(BSZ * KDIM / (256 * 4), 1, 2), 256>>>(input, h_prev);
    cast_wt_kernel<<<dim3(N4 / 32, KDIM / 32, 2), dim3(32, 8)>>>(w_i2h, w_h2h);

    // GEMMs on tensor pipe (mma.sync fp16, K=1024, 512 threads)
    cudaFuncSetAttribute(gemm_mma_kernel,
                         cudaFuncAttributeMaxDynamicSharedMemorySize, GEMM_SMEM);
    gemm_mma_kernel<<<dim3(N4 / BN, BSZ / BM, 2), 512, GEMM_SMEM>>>(b_i2h, b_h2h);

    ln_lstm_kernel<<<BSZ, 256>>>(c_prev, gi2h, bei2h, gh2h, beh2h, gc, bec,
                                 out_h, out_c);
}

// round 9
// speedup vs baseline: 6.0478x; 1.0966x over previous
#include <cuda_runtime.h>
#include <cuda_fp16.h>
#include <math.h>
#include <stdint.h>

// Problem dims (fixed)
#define BSZ   4096
#define KDIM  1024
#define N4    4096   // 4*H
#define HDIM  1024

// ---------------------------------------------------------------------------
// Device scratch (static, no dynamic allocation)
// ---------------------------------------------------------------------------
// Pre-LN gate buffers now fp16 (halves DRAM traffic of GEMM store + LN load)
__device__ __half g_gi[(size_t)BSZ * N4];   // input  @ w_i2h + b_i2h
__device__ __half g_gh[(size_t)BSZ * N4];   // h_prev @ w_h2h + b_h2h

// fp16 operands: A [BSZ, KDIM], W transposed [N4, KDIM]
__device__ __half g_a2[2][(size_t)BSZ * KDIM];
__device__ __half g_w2[2][(size_t)N4 * KDIM];

// ---------------------------------------------------------------------------
// Base-PTX helpers (legal on compute_103 virtual arch)
// ---------------------------------------------------------------------------
__device__ __forceinline__ uint32_t smem_u32(const void* p) {
    uint32_t a;
    asm("{ .reg .u64 t; cvta.to.shared.u64 t, %1; cvt.u32.u64 %0, t; }" : "=r"(a) : "l"(p));
    return a;
}
__device__ __forceinline__ void cp_async16(uint32_t s, const void* g) {
    asm volatile("cp.async.cg.shared.global [%0], [%1], 16;" :: "r"(s), "l"(g));
}
#define CP_COMMIT() asm volatile("cp.async.commit_group;" ::: "memory")
#define CP_WAIT(n)  asm volatile("cp.async.wait_group %0;" :: "n"(n) : "memory")

__device__ __forceinline__ void ldsm4(uint32_t& r0, uint32_t& r1, uint32_t& r2, uint32_t& r3,
                                      uint32_t addr) {
    asm volatile("ldmatrix.sync.aligned.m8n8.x4.shared.b16 {%0,%1,%2,%3}, [%4];"
                 : "=r"(r0), "=r"(r1), "=r"(r2), "=r"(r3) : "r"(addr));
}
__device__ __forceinline__ void mma_f16(float* c, const uint32_t* a, const uint32_t* b) {
    asm volatile(
        "mma.sync.aligned.m16n8k16.row.col.f32.f16.f16.f32 "
        "{%0,%1,%2,%3}, {%4,%5,%6,%7}, {%8,%9}, {%0,%1,%2,%3};"
        : "+f"(c[0]), "+f"(c[1]), "+f"(c[2]), "+f"(c[3])
        : "r"(a[0]), "r"(a[1]), "r"(a[2]), "r"(a[3]), "r"(b[0]), "r"(b[1]));
}

// ---------------------------------------------------------------------------
// Conversion kernels
// ---------------------------------------------------------------------------
__global__ void __launch_bounds__(256) cast_act_kernel(
    const float* __restrict__ src0, const float* __restrict__ src1)
{
    const int plane = blockIdx.z;
    const float* __restrict__ src = plane ? src1 : src0;
    __half* __restrict__ dst = g_a2[plane];

    const size_t idx = ((size_t)blockIdx.x * 256 + threadIdx.x) * 4;
    float4 v = *(const float4*)(src + idx);
    union { __half2 h2v[2]; uint2 u; } p;
    p.h2v[0] = __floats2half2_rn(v.x, v.y);
    p.h2v[1] = __floats2half2_rn(v.z, v.w);
    *(uint2*)(dst + idx) = p.u;
}

// Weights: W [KDIM, N4] fp32 -> W2 [N4, KDIM] fp16 (transpose)
__global__ void __launch_bounds__(256) cast_wt_kernel(
    const float* __restrict__ w0, const float* __restrict__ w1)
{
    const int plane = blockIdx.z;
    const float* __restrict__ W = plane ? w1 : w0;
    __half* __restrict__ D = g_w2[plane];

    __shared__ float tile[32][33];
    const int tx = threadIdx.x;          // 0..31
    const int ty = threadIdx.y;          // 0..7
    const int n0 = blockIdx.x * 32;      // N tile
    const int k0 = blockIdx.y * 32;      // K tile

    #pragma unroll
    for (int j = 0; j < 4; j++) {
        const int k = k0 + ty + j * 8;
        tile[ty + j * 8][tx] = W[(size_t)k * N4 + n0 + tx];
    }
    __syncthreads();
    #pragma unroll
    for (int j = 0; j < 4; j++) {
        const int n = n0 + ty + j * 8;
        D[(size_t)n * KDIM + k0 + tx] = __float2half(tile[tx][ty + j * 8]);
    }
}

// ---------------------------------------------------------------------------
// fp16 mma.sync GEMM: C[4096, 4096] = A[4096,1024] @ W[4096,1024]^T + bias
// CTA tile 128x256, BK=32, 512 threads (16 warps, 4x4), warp tile 32x64,
// 4-stage cp.async pipeline (3 in flight). Output stored fp16.
// ---------------------------------------------------------------------------
#define BM 128
#define BN 256
#define BK 32
#define STAGES 4
#define A_ST ((BM) * (BK) * 2)                  // 8192 B
#define B_ST ((BN) * (BK) * 2)                  // 16384 B
#define STAGE_BYTES (A_ST + B_ST)               // 24576 B
#define GEMM_SMEM (STAGES * STAGE_BYTES)        // 98304 B
#define ITERS (KDIM / BK)                       // 32

// smem row = 64B (32 fp16), 4 chunks of 16B; chunk' = chunk ^ ((r>>1)&3)
__device__ __forceinline__ uint32_t sw_off(int r, int chunk) {
    return (uint32_t)(r * 64 + ((chunk ^ ((r >> 1) & 3)) << 4));
}

__device__ __forceinline__ void load_stage(
    uint32_t sA, uint32_t sB,
    const __half* __restrict__ Ag, const __half* __restrict__ Wg,
    int m0, int n0, int kt, int tid)
{
    const int kbase = kt * BK;
    {                                             // A: 512 chunks / 512 thr
        const int r = tid >> 2, kc = tid & 3;
        cp_async16(sA + sw_off(r, kc), Ag + (size_t)(m0 + r) * KDIM + kbase + kc * 8);
    }
    #pragma unroll
    for (int i = 0; i < 2; i++) {                 // B: 1024 chunks / 512 thr
        const int id = tid + i * 512;
        const int r = id >> 2, kc = id & 3;
        cp_async16(sB + sw_off(r, kc), Wg + (size_t)(n0 + r) * KDIM + kbase + kc * 8);
    }
}

__global__ void __launch_bounds__(512, 1) gemm_mma_kernel(
    const float* __restrict__ bias0, const float* __restrict__ bias1)
{
    extern __shared__ char smem[];
    const uint32_t sbase = smem_u32(smem);
    const int tid  = threadIdx.x;
    const int lane = tid & 31;
    const int wid  = tid >> 5;
    const int wm   = wid >> 2;     // 0..3 -> m offset 32*wm
    const int wn   = wid & 3;      // 0..3 -> n offset 64*wn

    const int gemm = blockIdx.z;
    const int m0 = blockIdx.y * BM;
    const int n0 = blockIdx.x * BN;

    const __half* __restrict__ Ag = g_a2[gemm];
    const __half* __restrict__ Wg = g_w2[gemm];
    __half* __restrict__ C = gemm ? g_gh : g_gi;
    const float* __restrict__ bias = gemm ? bias1 : bias0;

    float acc[2][8][4];
    #pragma unroll
    for (int i = 0; i < 2; i++)
        #pragma unroll
        for (int j = 0; j < 8; j++)
            #pragma unroll
            for (int r = 0; r < 4; r++)
                acc[i][j][r] = 0.0f;

    const int row_a  = lane & 15;
    const int ksel_a = lane >> 4;
    const int row_b  = ((lane >> 4) << 3) | (lane & 7);
    const int ksel_b = (lane >> 3) & 1;

    load_stage(sbase,                   sbase + A_ST,                   Ag, Wg, m0, n0, 0, tid);
    CP_COMMIT();
    load_stage(sbase + STAGE_BYTES,     sbase + STAGE_BYTES + A_ST,     Ag, Wg, m0, n0, 1, tid);
    CP_COMMIT();
    load_stage(sbase + 2 * STAGE_BYTES, sbase + 2 * STAGE_BYTES + A_ST, Ag, Wg, m0, n0, 2, tid);
    CP_COMMIT();

    #pragma unroll 1
    for (int kt = 0; kt < ITERS; kt++) {
        CP_WAIT(2);
        __syncthreads();
        const int s = kt & 3;
        const uint32_t sA = sbase + s * STAGE_BYTES;
        const uint32_t sB = sA + A_ST;

        #pragma unroll
        for (int ks = 0; ks < 2; ks++) {
            uint32_t a[2][4], b[4][4];
            #pragma unroll
            for (int mt = 0; mt < 2; mt++) {
                const int r = wm * 32 + mt * 16 + row_a;
                ldsm4(a[mt][0], a[mt][1], a[mt][2], a[mt][3],
                      sA + sw_off(r, ks * 2 + ksel_a));
            }
            #pragma unroll
            for (int bt = 0; bt < 4; bt++) {
                const int n = wn * 64 + bt * 16 + row_b;
                ldsm4(b[bt][0], b[bt][1], b[bt][2], b[bt][3],
                      sB + sw_off(n, ks * 2 + ksel_b));
            }
            #pragma unroll
            for (int mt = 0; mt < 2; mt++)
                #pragma unroll
                for (int bt = 0; bt < 4; bt++) {
                    mma_f16(acc[mt][bt * 2],     a[mt], &b[bt][0]);
                    mma_f16(acc[mt][bt * 2 + 1], a[mt], &b[bt][2]);
                }
        }

        if (kt + 3 < ITERS) {
            const int sn = (kt + 3) & 3;
            load_stage(sbase + sn * STAGE_BYTES, sbase + sn * STAGE_BYTES + A_ST,
                       Ag, Wg, m0, n0, kt + 3, tid);
        }
        CP_COMMIT();
    }

    // epilogue: bias add (fp32) + store fp16
    float2 bv[8];
    #pragma unroll
    for (int nf = 0; nf < 8; nf++) {
        const int n = n0 + wn * 64 + nf * 8 + (lane & 3) * 2;
        bv[nf] = *(const float2*)(bias + n);
    }
    #pragma unroll
    for (int mt = 0; mt < 2; mt++) {
        const int m = m0 + wm * 32 + mt * 16 + (lane >> 2);
        #pragma unroll
        for (int nf = 0; nf < 8; nf++) {
            const int n = n0 + wn * 64 + nf * 8 + (lane & 3) * 2;
            const __half2 o0 = __floats2half2_rn(acc[mt][nf][0] + bv[nf].x,
                                                 acc[mt][nf][1] + bv[nf].y);
            const __half2 o1 = __floats2half2_rn(acc[mt][nf][2] + bv[nf].x,
                                                 acc[mt][nf][3] + bv[nf].y);
            *(__half2*)&C[(size_t)m * N4 + n]       = o0;
            *(__half2*)&C[(size_t)(m + 8) * N4 + n] = o1;
        }
    }
}

// ---------------------------------------------------------------------------
// Fused LayerNorm + LSTM gates, fp16 gate inputs (half2 loads).
// One block (256 threads) per row. half2 index h = k*256 + t (k<8) covers the
// row; gate g = k>>1, within-gate half2 pos p = (k&1)*256 + t, element cols
// j = 2p, 2p+1. For fixed (kk=k&1, t), gates g=0..3 share columns -> gate math
// stays intra-thread.
// ---------------------------------------------------------------------------
__device__ __forceinline__ float4 block_reduce_sum4(float4 v)
{
    __shared__ float4 sbuf[8];
    const int lane = threadIdx.x & 31;
    const int warp = threadIdx.x >> 5;
    #pragma unroll
    for (int o = 16; o > 0; o >>= 1) {
        v.x += __shfl_down_sync(0xffffffffu, v.x, o);
        v.y += __shfl_down_sync(0xffffffffu, v.y, o);
        v.z += __shfl_down_sync(0xffffffffu, v.z, o);
        v.w += __shfl_down_sync(0xffffffffu, v.w, o);
    }
    if (lane == 0) sbuf[warp] = v;
    __syncthreads();
    if (warp == 0) {
        v = (lane < 8) ? sbuf[lane] : make_float4(0.f, 0.f, 0.f, 0.f);
        #pragma unroll
        for (int o = 4; o > 0; o >>= 1) {
            v.x += __shfl_down_sync(0xffffffffu, v.x, o);
            v.y += __shfl_down_sync(0xffffffffu, v.y, o);
            v.z += __shfl_down_sync(0xffffffffu, v.z, o);
            v.w += __shfl_down_sync(0xffffffffu, v.w, o);
        }
        if (lane == 0) sbuf[0] = v;
    }
    __syncthreads();
    float4 res = sbuf[0];
    __syncthreads();
    return res;
}

__device__ __forceinline__ float sigmoidf_(float x) { return 1.0f / (1.0f + expf(-x)); }

__global__ void __launch_bounds__(256) ln_lstm_kernel(
    const float* __restrict__ c_prev,
    const float* __restrict__ g_i2h,  const float* __restrict__ be_i2h,
    const float* __restrict__ g_h2h,  const float* __restrict__ be_h2h,
    const float* __restrict__ g_c,    const float* __restrict__ be_c,
    float* __restrict__ out_h, float* __restrict__ out_c)
{
    const int row = blockIdx.x;
    const int t   = threadIdx.x;
    const __half2* gi = (const __half2*)g_gi + (size_t)row * (N4 / 2);
    const __half2* gh = (const __half2*)g_gh + (size_t)row * (N4 / 2);

    float2 vi[8], vh[8];
    float4 s = make_float4(0.f, 0.f, 0.f, 0.f);
    #pragma unroll
    for (int k = 0; k < 8; k++) {
        const int h = k * 256 + t;
        const float2 a = __half22float2(gi[h]);
        const float2 b = __half22float2(gh[h]);
        vi[k] = a; vh[k] = b;
        s.x += a.x + a.y; s.y += a.x * a.x + a.y * a.y;
        s.z += b.x + b.y; s.w += b.x * b.x + b.y * b.y;
    }
    s = block_reduce_sum4(s);

    const float n1  = (float)N4;
    const float mi  = s.x / n1;
    const float mh  = s.z / n1;
    const float var_i = (s.y - n1 * mi * mi) / (n1 - 1.0f);
    const float var_h = (s.w - n1 * mh * mh) / (n1 - 1.0f);
    const float inv_i = 1.0f / (sqrtf(fmaxf(var_i, 0.f)) + 1e-6f);
    const float inv_h = 1.0f / (sqrtf(fmaxf(var_h, 0.f)) + 1e-6f);

    // normalized gate sums, element pair per k
    float sg[8][2];
    #pragma unroll
    for (int k = 0; k < 8; k++) {
        const int g = k >> 1;
        const int j = (((k & 1) * 256 + t) << 1);       // within-gate column base
        const int pidx = g * 1024 + j;
        const float2 ga = *(const float2*)(g_i2h + pidx);
        const float2 ba = *(const float2*)(be_i2h + pidx);
        const float2 gb = *(const float2*)(g_h2h + pidx);
        const float2 bb = *(const float2*)(be_h2h + pidx);
        sg[k][0] = ga.x * (vi[k].x - mi) * inv_i + ba.x + gb.x * (vh[k].x - mh) * inv_h + bb.x;
        sg[k][1] = ga.y * (vi[k].y - mi) * inv_i + ba.y + gb.y * (vh[k].y - mh) * inv_h + bb.y;
    }

    // gates: for kk in {0,1}: i=sg[kk], f=sg[2+kk], u=sg[4+kk], o=sg[6+kk]
    float cn[2][2];
    float4 cs = make_float4(0.f, 0.f, 0.f, 0.f);
    #pragma unroll
    for (int kk = 0; kk < 2; kk++) {
        const int j = ((kk * 256 + t) << 1);
        const float2 cp = *(const float2*)(c_prev + (size_t)row * HDIM + j);
        const float cpv[2] = {cp.x, cp.y};
        #pragma unroll
        for (int x = 0; x < 2; x++) {
            const float ig = sg[kk][x];
            const float fg = sg[2 + kk][x];
            const float ug = sg[4 + kk][x];
            cn[kk][x] = cpv[x] * sigmoidf_(fg + 1.0f) + tanhf(ug) * sigmoidf_(ig);
            cs.x += cn[kk][x];
            cs.y += cn[kk][x] * cn[kk][x];
        }
    }
    cs = block_reduce_sum4(cs);

    const float n2   = (float)HDIM;
    const float mc   = cs.x / n2;
    const float var_c = (cs.y - n2 * mc * mc) / (n2 - 1.0f);
    const float inv_c = 1.0f / (sqrtf(fmaxf(var_c, 0.f)) + 1e-6f);

    #pragma unroll
    for (int kk = 0; kk < 2; kk++) {
        const int j = ((kk * 256 + t) << 1);
        const float2 gcv  = *(const float2*)(g_c + j);
        const float2 becv = *(const float2*)(be_c + j);
        float2 oc, oh;
        oc.x = gcv.x * (cn[kk][0] - mc) * inv_c + becv.x;
        oc.y = gcv.y * (cn[kk][1] - mc) * inv_c + becv.y;
        oh.x = sigmoidf_(sg[6 + kk][0]) * tanhf(oc.x);
        oh.y = sigmoidf_(sg[6 + kk][1]) * tanhf(oc.y);
        *(float2*)(out_c + (size_t)row * HDIM + j) = oc;
        *(float2*)(out_h + (size_t)row * HDIM + j) = oh;
    }
}

// ---------------------------------------------------------------------------
extern "C" void kernel_launch(void* const* d_in, const int* in_sizes, int n_in,
                              void* d_out, int out_size)
{
    const float* input  = (const float*)d_in[0];
    const float* h_prev = (const float*)d_in[1];
    const float* c_prev = (const float*)d_in[2];
    const float* w_i2h  = (const float*)d_in[3];
    const float* b_i2h  = (const float*)d_in[4];
    const float* w_h2h  = (const float*)d_in[5];
    const float* b_h2h  = (const float*)d_in[6];
    const float* gi2h   = (const float*)d_in[7];
    const float* bei2h  = (const float*)d_in[8];
    const float* gh2h   = (const float*)d_in[9];
    const float* beh2h  = (const float*)d_in[10];
    const float* gc     = (const float*)d_in[11];
    const float* bec    = (const float*)d_in[12];

    float* out_h = (float*)d_out;
    float* out_c = (float*)d_out + (size_t)BSZ * HDIM;

    // conversions
    cast_act_kernel<<<dim3(BSZ * KDIM / (256 * 4), 1, 2), 256>>>(input, h_prev);
    cast_wt_kernel<<<dim3(N4 / 32, KDIM / 32, 2), dim3(32, 8)>>>(w_i2h, w_h2h);

    // GEMMs on tensor pipe (mma.sync fp16, K=1024, 512 threads, 4 stages)
    cudaFuncSetAttribute(gemm_mma_kernel,
                         cudaFuncAttributeMaxDynamicSharedMemorySize, GEMM_SMEM);
    gemm_mma_kernel<<<dim3(N4 / BN, BSZ / BM, 2), 512, GEMM_SMEM>>>(b_i2h, b_h2h);

    ln_lstm_kernel<<<BSZ, 256>>>(c_prev, gi2h, bei2h, gh2h, beh2h, gc, bec,
                                 out_h, out_c);
}

// round 10
// speedup vs baseline: 6.2731x; 1.0373x over previous
#include <cuda_runtime.h>
#include <cuda_fp16.h>
#include <math.h>
#include <stdint.h>

// Problem dims (fixed)
#define BSZ   4096
#define KDIM  1024
#define N4    4096   // 4*H
#define HDIM  1024

// ---------------------------------------------------------------------------
// Device scratch (static, no dynamic allocation)
// ---------------------------------------------------------------------------
__device__ __half g_gi[(size_t)BSZ * N4];   // input  @ w_i2h + b_i2h (fp16)
__device__ __half g_gh[(size_t)BSZ * N4];   // h_prev @ w_h2h + b_h2h (fp16)

// fp16 operands: A [BSZ, KDIM], W transposed [N4, KDIM]
__device__ __half g_a2[2][(size_t)BSZ * KDIM];
__device__ __half g_w2[2][(size_t)N4 * KDIM];

// ---------------------------------------------------------------------------
// Base-PTX helpers (legal on compute_103 virtual arch)
// ---------------------------------------------------------------------------
__device__ __forceinline__ uint32_t smem_u32(const void* p) {
    uint32_t a;
    asm("{ .reg .u64 t; cvta.to.shared.u64 t, %1; cvt.u32.u64 %0, t; }" : "=r"(a) : "l"(p));
    return a;
}
__device__ __forceinline__ void cp_async16(uint32_t s, const void* g) {
    asm volatile("cp.async.cg.shared.global [%0], [%1], 16;" :: "r"(s), "l"(g));
}
#define CP_COMMIT() asm volatile("cp.async.commit_group;" ::: "memory")
#define CP_WAIT(n)  asm volatile("cp.async.wait_group %0;" :: "n"(n) : "memory")

__device__ __forceinline__ void ldsm4(uint32_t& r0, uint32_t& r1, uint32_t& r2, uint32_t& r3,
                                      uint32_t addr) {
    asm volatile("ldmatrix.sync.aligned.m8n8.x4.shared.b16 {%0,%1,%2,%3}, [%4];"
                 : "=r"(r0), "=r"(r1), "=r"(r2), "=r"(r3) : "r"(addr));
}
__device__ __forceinline__ void mma_f16(float* c, const uint32_t* a, const uint32_t* b) {
    asm volatile(
        "mma.sync.aligned.m16n8k16.row.col.f32.f16.f16.f32 "
        "{%0,%1,%2,%3}, {%4,%5,%6,%7}, {%8,%9}, {%0,%1,%2,%3};"
        : "+f"(c[0]), "+f"(c[1]), "+f"(c[2]), "+f"(c[3])
        : "r"(a[0]), "r"(a[1]), "r"(a[2]), "r"(a[3]), "r"(b[0]), "r"(b[1]));
}

// fast transcendental approximations (single MUFU op each)
__device__ __forceinline__ float fast_tanh(float x) {
    float y;
    asm("tanh.approx.f32 %0, %1;" : "=f"(y) : "f"(x));
    return y;
}
__device__ __forceinline__ float fast_sigmoid(float x) {
    float e;
    asm("ex2.approx.f32 %0, %1;" : "=f"(e) : "f"(-1.4426950408889634f * x));
    float r;
    asm("rcp.approx.f32 %0, %1;" : "=f"(r) : "f"(1.0f + e));
    return r;
}

// ---------------------------------------------------------------------------
// Conversion kernels
// ---------------------------------------------------------------------------
__global__ void __launch_bounds__(256) cast_act_kernel(
    const float* __restrict__ src0, const float* __restrict__ src1)
{
    const int plane = blockIdx.z;
    const float* __restrict__ src = plane ? src1 : src0;
    __half* __restrict__ dst = g_a2[plane];

    const size_t idx = ((size_t)blockIdx.x * 256 + threadIdx.x) * 4;
    float4 v = *(const float4*)(src + idx);
    union { __half2 h2v[2]; uint2 u; } p;
    p.h2v[0] = __floats2half2_rn(v.x, v.y);
    p.h2v[1] = __floats2half2_rn(v.z, v.w);
    *(uint2*)(dst + idx) = p.u;
}

// Weights: W [KDIM, N4] fp32 -> W2 [N4, KDIM] fp16 (transpose), vectorized.
// Tile 32(K) x 32(N). Pass 1: float4 global reads -> transposed smem (pad 33,
// conflict-free). Pass 2: 16B global writes (8 halfs along K).
__global__ void __launch_bounds__(128) cast_wt_kernel(
    const float* __restrict__ w0, const float* __restrict__ w1)
{
    const int plane = blockIdx.z;
    const float* __restrict__ W = plane ? w1 : w0;
    __half* __restrict__ D = g_w2[plane];

    __shared__ float tileT[32][33];      // [n][k]
    const int tid = threadIdx.x;
    const int n0 = blockIdx.x * 32;      // N tile
    const int k0 = blockIdx.y * 32;      // K tile

    // Pass 1: 32x32 floats = 256 float4; 128 threads -> 2 each
    #pragma unroll
    for (int it = 0; it < 2; it++) {
        const int id = tid + it * 128;
        const int k  = id >> 3;              // 0..31
        const int n4 = (id & 7) * 4;         // 0,4,..28
        const float4 v = *(const float4*)(W + (size_t)(k0 + k) * N4 + n0 + n4);
        tileT[n4 + 0][k] = v.x;
        tileT[n4 + 1][k] = v.y;
        tileT[n4 + 2][k] = v.z;
        tileT[n4 + 3][k] = v.w;
    }
    __syncthreads();

    // Pass 2: 32 rows x 4 chunks(16B) = 128 chunks; 1 per thread
    const int n  = tid >> 2;                 // 0..31
    const int kc = (tid & 3) * 8;            // 0,8,16,24
    union { __half2 h[4]; uint4 u; } o;
    #pragma unroll
    for (int i = 0; i < 4; i++)
        o.h[i] = __floats2half2_rn(tileT[n][kc + i * 2], tileT[n][kc + i * 2 + 1]);
    *(uint4*)(D + (size_t)(n0 + n) * KDIM + k0 + kc) = o.u;
}

// ---------------------------------------------------------------------------
// fp16 mma.sync GEMM: C[4096, 4096] = A[4096,1024] @ W[4096,1024]^T + bias
// CTA tile 128x256, BK=32, 512 threads (16 warps, 4x4), warp tile 32x64,
// 4-stage cp.async pipeline (3 in flight). Output stored fp16.
// ---------------------------------------------------------------------------
#define BM 128
#define BN 256
#define BK 32
#define STAGES 4
#define A_ST ((BM) * (BK) * 2)                  // 8192 B
#define B_ST ((BN) * (BK) * 2)                  // 16384 B
#define STAGE_BYTES (A_ST + B_ST)               // 24576 B
#define GEMM_SMEM (STAGES * STAGE_BYTES)        // 98304 B
#define ITERS (KDIM / BK)                       // 32

// smem row = 64B (32 fp16), 4 chunks of 16B; chunk' = chunk ^ ((r>>1)&3)
__device__ __forceinline__ uint32_t sw_off(int r, int chunk) {
    return (uint32_t)(r * 64 + ((chunk ^ ((r >> 1) & 3)) << 4));
}

__device__ __forceinline__ void load_stage(
    uint32_t sA, uint32_t sB,
    const __half* __restrict__ Ag, const __half* __restrict__ Wg,
    int m0, int n0, int kt, int tid)
{
    const int kbase = kt * BK;
    {                                             // A: 512 chunks / 512 thr
        const int r = tid >> 2, kc = tid & 3;
        cp_async16(sA + sw_off(r, kc), Ag + (size_t)(m0 + r) * KDIM + kbase + kc * 8);
    }
    #pragma unroll
    for (int i = 0; i < 2; i++) {                 // B: 1024 chunks / 512 thr
        const int id = tid + i * 512;
        const int r = id >> 2, kc = id & 3;
        cp_async16(sB + sw_off(r, kc), Wg + (size_t)(n0 + r) * KDIM + kbase + kc * 8);
    }
}

__global__ void __launch_bounds__(512, 1) gemm_mma_kernel(
    const float* __restrict__ bias0, const float* __restrict__ bias1)
{
    extern __shared__ char smem[];
    const uint32_t sbase = smem_u32(smem);
    const int tid  = threadIdx.x;
    const int lane = tid & 31;
    const int wid  = tid >> 5;
    const int wm   = wid >> 2;     // 0..3 -> m offset 32*wm
    const int wn   = wid & 3;      // 0..3 -> n offset 64*wn

    const int gemm = blockIdx.z;
    const int m0 = blockIdx.y * BM;
    const int n0 = blockIdx.x * BN;

    const __half* __restrict__ Ag = g_a2[gemm];
    const __half* __restrict__ Wg = g_w2[gemm];
    __half* __restrict__ C = gemm ? g_gh : g_gi;
    const float* __restrict__ bias = gemm ? bias1 : bias0;

    float acc[2][8][4];
    #pragma unroll
    for (int i = 0; i < 2; i++)
        #pragma unroll
        for (int j = 0; j < 8; j++)
            #pragma unroll
            for (int r = 0; r < 4; r++)
                acc[i][j][r] = 0.0f;

    const int row_a  = lane & 15;
    const int ksel_a = lane >> 4;
    const int row_b  = ((lane >> 4) << 3) | (lane & 7);
    const int ksel_b = (lane >> 3) & 1;

    load_stage(sbase,                   sbase + A_ST,                   Ag, Wg, m0, n0, 0, tid);
    CP_COMMIT();
    load_stage(sbase + STAGE_BYTES,     sbase + STAGE_BYTES + A_ST,     Ag, Wg, m0, n0, 1, tid);
    CP_COMMIT();
    load_stage(sbase + 2 * STAGE_BYTES, sbase + 2 * STAGE_BYTES + A_ST, Ag, Wg, m0, n0, 2, tid);
    CP_COMMIT();

    #pragma unroll 1
    for (int kt = 0; kt < ITERS; kt++) {
        CP_WAIT(2);
        __syncthreads();
        const int s = kt & 3;
        const uint32_t sA = sbase + s * STAGE_BYTES;
        const uint32_t sB = sA + A_ST;

        #pragma unroll
        for (int ks = 0; ks < 2; ks++) {
            uint32_t a[2][4], b[4][4];
            #pragma unroll
            for (int mt = 0; mt < 2; mt++) {
                const int r = wm * 32 + mt * 16 + row_a;
                ldsm4(a[mt][0], a[mt][1], a[mt][2], a[mt][3],
                      sA + sw_off(r, ks * 2 + ksel_a));
            }
            #pragma unroll
            for (int bt = 0; bt < 4; bt++) {
                const int n = wn * 64 + bt * 16 + row_b;
                ldsm4(b[bt][0], b[bt][1], b[bt][2], b[bt][3],
                      sB + sw_off(n, ks * 2 + ksel_b));
            }
            #pragma unroll
            for (int mt = 0; mt < 2; mt++)
                #pragma unroll
                for (int bt = 0; bt < 4; bt++) {
                    mma_f16(acc[mt][bt * 2],     a[mt], &b[bt][0]);
                    mma_f16(acc[mt][bt * 2 + 1], a[mt], &b[bt][2]);
                }
        }

        if (kt + 3 < ITERS) {
            const int sn = (kt + 3) & 3;
            load_stage(sbase + sn * STAGE_BYTES, sbase + sn * STAGE_BYTES + A_ST,
                       Ag, Wg, m0, n0, kt + 3, tid);
        }
        CP_COMMIT();
    }

    // epilogue: bias add (fp32) + store fp16
    float2 bv[8];
    #pragma unroll
    for (int nf = 0; nf < 8; nf++) {
        const int n = n0 + wn * 64 + nf * 8 + (lane & 3) * 2;
        bv[nf] = *(const float2*)(bias + n);
    }
    #pragma unroll
    for (int mt = 0; mt < 2; mt++) {
        const int m = m0 + wm * 32 + mt * 16 + (lane >> 2);
        #pragma unroll
        for (int nf = 0; nf < 8; nf++) {
            const int n = n0 + wn * 64 + nf * 8 + (lane & 3) * 2;
            const __half2 o0 = __floats2half2_rn(acc[mt][nf][0] + bv[nf].x,
                                                 acc[mt][nf][1] + bv[nf].y);
            const __half2 o1 = __floats2half2_rn(acc[mt][nf][2] + bv[nf].x,
                                                 acc[mt][nf][3] + bv[nf].y);
            *(__half2*)&C[(size_t)m * N4 + n]       = o0;
            *(__half2*)&C[(size_t)(m + 8) * N4 + n] = o1;
        }
    }
}

// ---------------------------------------------------------------------------
// Fused LayerNorm + LSTM gates, fp16 gate inputs, MUFU-approx transcendentals
// ---------------------------------------------------------------------------
__device__ __forceinline__ float4 block_reduce_sum4(float4 v)
{
    __shared__ float4 sbuf[8];
    const int lane = threadIdx.x & 31;
    const int warp = threadIdx.x >> 5;
    #pragma unroll
    for (int o = 16; o > 0; o >>= 1) {
        v.x += __shfl_down_sync(0xffffffffu, v.x, o);
        v.y += __shfl_down_sync(0xffffffffu, v.y, o);
        v.z += __shfl_down_sync(0xffffffffu, v.z, o);
        v.w += __shfl_down_sync(0xffffffffu, v.w, o);
    }
    if (lane == 0) sbuf[warp] = v;
    __syncthreads();
    if (warp == 0) {
        v = (lane < 8) ? sbuf[lane] : make_float4(0.f, 0.f, 0.f, 0.f);
        #pragma unroll
        for (int o = 4; o > 0; o >>= 1) {
            v.x += __shfl_down_sync(0xffffffffu, v.x, o);
            v.y += __shfl_down_sync(0xffffffffu, v.y, o);
            v.z += __shfl_down_sync(0xffffffffu, v.z, o);
            v.w += __shfl_down_sync(0xffffffffu, v.w, o);
        }
        if (lane == 0) sbuf[0] = v;
    }
    __syncthreads();
    float4 res = sbuf[0];
    __syncthreads();
    return res;
}

__global__ void __launch_bounds__(256) ln_lstm_kernel(
    const float* __restrict__ c_prev,
    const float* __restrict__ g_i2h,  const float* __restrict__ be_i2h,
    const float* __restrict__ g_h2h,  const float* __restrict__ be_h2h,
    const float* __restrict__ g_c,    const float* __restrict__ be_c,
    float* __restrict__ out_h, float* __restrict__ out_c)
{
    const int row = blockIdx.x;
    const int t   = threadIdx.x;
    const __half2* gi = (const __half2*)g_gi + (size_t)row * (N4 / 2);
    const __half2* gh = (const __half2*)g_gh + (size_t)row * (N4 / 2);

    float2 vi[8], vh[8];
    float4 s = make_float4(0.f, 0.f, 0.f, 0.f);
    #pragma unroll
    for (int k = 0; k < 8; k++) {
        const int h = k * 256 + t;
        const float2 a = __half22float2(gi[h]);
        const float2 b = __half22float2(gh[h]);
        vi[k] = a; vh[k] = b;
        s.x += a.x + a.y; s.y += a.x * a.x + a.y * a.y;
        s.z += b.x + b.y; s.w += b.x * b.x + b.y * b.y;
    }
    s = block_reduce_sum4(s);

    const float n1  = (float)N4;
    const float mi  = s.x / n1;
    const float mh  = s.z / n1;
    const float var_i = (s.y - n1 * mi * mi) / (n1 - 1.0f);
    const float var_h = (s.w - n1 * mh * mh) / (n1 - 1.0f);
    const float inv_i = 1.0f / (sqrtf(fmaxf(var_i, 0.f)) + 1e-6f);
    const float inv_h = 1.0f / (sqrtf(fmaxf(var_h, 0.f)) + 1e-6f);

    float sg[8][2];
    #pragma unroll
    for (int k = 0; k < 8; k++) {
        const int g = k >> 1;
        const int j = (((k & 1) * 256 + t) << 1);
        const int pidx = g * 1024 + j;
        const float2 ga = *(const float2*)(g_i2h + pidx);
        const float2 ba = *(const float2*)(be_i2h + pidx);
        const float2 gb = *(const float2*)(g_h2h + pidx);
        const float2 bb = *(const float2*)(be_h2h + pidx);
        sg[k][0] = ga.x * (vi[k].x - mi) * inv_i + ba.x + gb.x * (vh[k].x - mh) * inv_h + bb.x;
        sg[k][1] = ga.y * (vi[k].y - mi) * inv_i + ba.y + gb.y * (vh[k].y - mh) * inv_h + bb.y;
    }

    float cn[2][2];
    float4 cs = make_float4(0.f, 0.f, 0.f, 0.f);
    #pragma unroll
    for (int kk = 0; kk < 2; kk++) {
        const int j = ((kk * 256 + t) << 1);
        const float2 cp = *(const float2*)(c_prev + (size_t)row * HDIM + j);
        const float cpv[2] = {cp.x, cp.y};
        #pragma unroll
        for (int x = 0; x < 2; x++) {
            const float ig = sg[kk][x];
            const float fg = sg[2 + kk][x];
            const float ug = sg[4 + kk][x];
            cn[kk][x] = cpv[x] * fast_sigmoid(fg + 1.0f) + fast_tanh(ug) * fast_sigmoid(ig);
            cs.x += cn[kk][x];
            cs.y += cn[kk][x] * cn[kk][x];
        }
    }
    cs = block_reduce_sum4(cs);

    const float n2   = (float)HDIM;
    const float mc   = cs.x / n2;
    const float var_c = (cs.y - n2 * mc * mc) / (n2 - 1.0f);
    const float inv_c = 1.0f / (sqrtf(fmaxf(var_c, 0.f)) + 1e-6f);

    #pragma unroll
    for (int kk = 0; kk < 2; kk++) {
        const int j = ((kk * 256 + t) << 1);
        const float2 gcv  = *(const float2*)(g_c + j);
        const float2 becv = *(const float2*)(be_c + j);
        float2 oc, oh;
        oc.x = gcv.x * (cn[kk][0] - mc) * inv_c + becv.x;
        oc.y = gcv.y * (cn[kk][1] - mc) * inv_c + becv.y;
        oh.x = fast_sigmoid(sg[6 + kk][0]) * fast_tanh(oc.x);
        oh.y = fast_sigmoid(sg[6 + kk][1]) * fast_tanh(oc.y);
        *(float2*)(out_c + (size_t)row * HDIM + j) = oc;
        *(float2*)(out_h + (size_t)row * HDIM + j) = oh;
    }
}

// ---------------------------------------------------------------------------
extern "C" void kernel_launch(void* const* d_in, const int* in_sizes, int n_in,
                              void* d_out, int out_size)
{
    const float* input  = (const float*)d_in[0];
    const float* h_prev = (const float*)d_in[1];
    const float* c_prev = (const float*)d_in[2];
    const float* w_i2h  = (const float*)d_in[3];
    const float* b_i2h  = (const float*)d_in[4];
    const float* w_h2h  = (const float*)d_in[5];
    const float* b_h2h  = (const float*)d_in[6];
    const float* gi2h   = (const float*)d_in[7];
    const float* bei2h  = (const float*)d_in[8];
    const float* gh2h   = (const float*)d_in[9];
    const float* beh2h  = (const float*)d_in[10];
    const float* gc     = (const float*)d_in[11];
    const float* bec    = (const float*)d_in[12];

    float* out_h = (float*)d_out;
    float* out_c = (float*)d_out + (size_t)BSZ * HDIM;

    // conversions
    cast_act_kernel<<<dim3(BSZ * KDIM / (256 * 4), 1, 2), 256>>>(input, h_prev);
    cast_wt_kernel<<<dim3(N4 / 32, KDIM / 32, 2), 128>>>(w_i2h, w_h2h);

    // GEMMs on tensor pipe (mma.sync fp16, K=1024, 512 threads, 4 stages)
    cudaFuncSetAttribute(gemm_mma_kernel,
                         cudaFuncAttributeMaxDynamicSharedMemorySize, GEMM_SMEM);
    gemm_mma_kernel<<<dim3(N4 / BN, BSZ / BM, 2), 512, GEMM_SMEM>>>(b_i2h, b_h2h);

    ln_lstm_kernel<<<BSZ, 256>>>(c_prev, gi2h, bei2h, gh2h, beh2h, gc, bec,
                                 out_h, out_c);
}

// round 11
// speedup vs baseline: 6.3191x; 1.0073x over previous
#include <cuda_runtime.h>
#include <cuda_fp16.h>
#include <math.h>
#include <stdint.h>

// Problem dims (fixed)
#define BSZ   4096
#define KDIM  1024
#define N4    4096   // 4*H
#define HDIM  1024

// ---------------------------------------------------------------------------
// Device scratch (static, no dynamic allocation)
// ---------------------------------------------------------------------------
__device__ __half g_gi[(size_t)BSZ * N4];   // input  @ w_i2h + b_i2h (fp16)
__device__ __half g_gh[(size_t)BSZ * N4];   // h_prev @ w_h2h + b_h2h (fp16)

// fp16 operands: A [BSZ, KDIM], W transposed [N4, KDIM]
__device__ __half g_a2[2][(size_t)BSZ * KDIM];
__device__ __half g_w2[2][(size_t)N4 * KDIM];

// ---------------------------------------------------------------------------
// Base-PTX helpers (legal on compute_103 virtual arch)
// ---------------------------------------------------------------------------
__device__ __forceinline__ uint32_t smem_u32(const void* p) {
    uint32_t a;
    asm("{ .reg .u64 t; cvta.to.shared.u64 t, %1; cvt.u32.u64 %0, t; }" : "=r"(a) : "l"(p));
    return a;
}
__device__ __forceinline__ void cp_async16(uint32_t s, const void* g) {
    asm volatile("cp.async.cg.shared.global [%0], [%1], 16;" :: "r"(s), "l"(g));
}
#define CP_COMMIT() asm volatile("cp.async.commit_group;" ::: "memory")
#define CP_WAIT(n)  asm volatile("cp.async.wait_group %0;" :: "n"(n) : "memory")

__device__ __forceinline__ void ldsm4(uint32_t& r0, uint32_t& r1, uint32_t& r2, uint32_t& r3,
                                      uint32_t addr) {
    asm volatile("ldmatrix.sync.aligned.m8n8.x4.shared.b16 {%0,%1,%2,%3}, [%4];"
                 : "=r"(r0), "=r"(r1), "=r"(r2), "=r"(r3) : "r"(addr));
}
__device__ __forceinline__ void mma_f16(float* c, const uint32_t* a, const uint32_t* b) {
    asm volatile(
        "mma.sync.aligned.m16n8k16.row.col.f32.f16.f16.f32 "
        "{%0,%1,%2,%3}, {%4,%5,%6,%7}, {%8,%9}, {%0,%1,%2,%3};"
        : "+f"(c[0]), "+f"(c[1]), "+f"(c[2]), "+f"(c[3])
        : "r"(a[0]), "r"(a[1]), "r"(a[2]), "r"(a[3]), "r"(b[0]), "r"(b[1]));
}

// fast transcendental approximations (single MUFU op each)
__device__ __forceinline__ float fast_tanh(float x) {
    float y;
    asm("tanh.approx.f32 %0, %1;" : "=f"(y) : "f"(x));
    return y;
}
__device__ __forceinline__ float fast_sigmoid(float x) {
    float e;
    asm("ex2.approx.f32 %0, %1;" : "=f"(e) : "f"(-1.4426950408889634f * x));
    float r;
    asm("rcp.approx.f32 %0, %1;" : "=f"(r) : "f"(1.0f + e));
    return r;
}
__device__ __forceinline__ float fast_sqrt(float x) {
    float y;
    asm("sqrt.approx.f32 %0, %1;" : "=f"(y) : "f"(x));
    return y;
}
__device__ __forceinline__ float fast_rcp(float x) {
    float y;
    asm("rcp.approx.f32 %0, %1;" : "=f"(y) : "f"(x));
    return y;
}

// ---------------------------------------------------------------------------
// Conversion kernels
// ---------------------------------------------------------------------------
__global__ void __launch_bounds__(256) cast_act_kernel(
    const float* __restrict__ src0, const float* __restrict__ src1)
{
    const int plane = blockIdx.z;
    const float* __restrict__ src = plane ? src1 : src0;
    __half* __restrict__ dst = g_a2[plane];

    const size_t idx = ((size_t)blockIdx.x * 256 + threadIdx.x) * 4;
    float4 v = *(const float4*)(src + idx);
    union { __half2 h2v[2]; uint2 u; } p;
    p.h2v[0] = __floats2half2_rn(v.x, v.y);
    p.h2v[1] = __floats2half2_rn(v.z, v.w);
    *(uint2*)(dst + idx) = p.u;
}

// Weights: W [KDIM, N4] fp32 -> W2 [N4, KDIM] fp16 (transpose), vectorized.
__global__ void __launch_bounds__(128) cast_wt_kernel(
    const float* __restrict__ w0, const float* __restrict__ w1)
{
    const int plane = blockIdx.z;
    const float* __restrict__ W = plane ? w1 : w0;
    __half* __restrict__ D = g_w2[plane];

    __shared__ float tileT[32][33];      // [n][k]
    const int tid = threadIdx.x;
    const int n0 = blockIdx.x * 32;      // N tile
    const int k0 = blockIdx.y * 32;      // K tile

    #pragma unroll
    for (int it = 0; it < 2; it++) {
        const int id = tid + it * 128;
        const int k  = id >> 3;              // 0..31
        const int n4 = (id & 7) * 4;         // 0,4,..28
        const float4 v = *(const float4*)(W + (size_t)(k0 + k) * N4 + n0 + n4);
        tileT[n4 + 0][k] = v.x;
        tileT[n4 + 1][k] = v.y;
        tileT[n4 + 2][k] = v.z;
        tileT[n4 + 3][k] = v.w;
    }
    __syncthreads();

    const int n  = tid >> 2;                 // 0..31
    const int kc = (tid & 3) * 8;            // 0,8,16,24
    union { __half2 h[4]; uint4 u; } o;
    #pragma unroll
    for (int i = 0; i < 4; i++)
        o.h[i] = __floats2half2_rn(tileT[n][kc + i * 2], tileT[n][kc + i * 2 + 1]);
    *(uint4*)(D + (size_t)(n0 + n) * KDIM + k0 + kc) = o.u;
}

// ---------------------------------------------------------------------------
// fp16 mma.sync GEMM: C[4096, 4096] = A[4096,1024] @ W[4096,1024]^T + bias
// CTA tile 128x256, BK=32, 512 threads (16 warps, 4x4), warp tile 32x64,
// 4-stage cp.async pipeline (3 in flight). Output stored fp16.
// ---------------------------------------------------------------------------
#define BM 128
#define BN 256
#define BK 32
#define STAGES 4
#define A_ST ((BM) * (BK) * 2)                  // 8192 B
#define B_ST ((BN) * (BK) * 2)                  // 16384 B
#define STAGE_BYTES (A_ST + B_ST)               // 24576 B
#define GEMM_SMEM (STAGES * STAGE_BYTES)        // 98304 B
#define ITERS (KDIM / BK)                       // 32

__device__ __forceinline__ uint32_t sw_off(int r, int chunk) {
    return (uint32_t)(r * 64 + ((chunk ^ ((r >> 1) & 3)) << 4));
}

__device__ __forceinline__ void load_stage(
    uint32_t sA, uint32_t sB,
    const __half* __restrict__ Ag, const __half* __restrict__ Wg,
    int m0, int n0, int kt, int tid)
{
    const int kbase = kt * BK;
    {
        const int r = tid >> 2, kc = tid & 3;
        cp_async16(sA + sw_off(r, kc), Ag + (size_t)(m0 + r) * KDIM + kbase + kc * 8);
    }
    #pragma unroll
    for (int i = 0; i < 2; i++) {
        const int id = tid + i * 512;
        const int r = id >> 2, kc = id & 3;
        cp_async16(sB + sw_off(r, kc), Wg + (size_t)(n0 + r) * KDIM + kbase + kc * 8);
    }
}

__global__ void __launch_bounds__(512, 1) gemm_mma_kernel(
    const float* __restrict__ bias0, const float* __restrict__ bias1)
{
    extern __shared__ char smem[];
    const uint32_t sbase = smem_u32(smem);
    const int tid  = threadIdx.x;
    const int lane = tid & 31;
    const int wid  = tid >> 5;
    const int wm   = wid >> 2;     // 0..3
    const int wn   = wid & 3;      // 0..3

    const int gemm = blockIdx.z;
    const int m0 = blockIdx.y * BM;
    const int n0 = blockIdx.x * BN;

    const __half* __restrict__ Ag = g_a2[gemm];
    const __half* __restrict__ Wg = g_w2[gemm];
    __half* __restrict__ C = gemm ? g_gh : g_gi;
    const float* __restrict__ bias = gemm ? bias1 : bias0;

    float acc[2][8][4];
    #pragma unroll
    for (int i = 0; i < 2; i++)
        #pragma unroll
        for (int j = 0; j < 8; j++)
            #pragma unroll
            for (int r = 0; r < 4; r++)
                acc[i][j][r] = 0.0f;

    const int row_a  = lane & 15;
    const int ksel_a = lane >> 4;
    const int row_b  = ((lane >> 4) << 3) | (lane & 7);
    const int ksel_b = (lane >> 3) & 1;

    load_stage(sbase,                   sbase + A_ST,                   Ag, Wg, m0, n0, 0, tid);
    CP_COMMIT();
    load_stage(sbase + STAGE_BYTES,     sbase + STAGE_BYTES + A_ST,     Ag, Wg, m0, n0, 1, tid);
    CP_COMMIT();
    load_stage(sbase + 2 * STAGE_BYTES, sbase + 2 * STAGE_BYTES + A_ST, Ag, Wg, m0, n0, 2, tid);
    CP_COMMIT();

    #pragma unroll 1
    for (int kt = 0; kt < ITERS; kt++) {
        CP_WAIT(2);
        __syncthreads();
        const int s = kt & 3;
        const uint32_t sA = sbase + s * STAGE_BYTES;
        const uint32_t sB = sA + A_ST;

        #pragma unroll
        for (int ks = 0; ks < 2; ks++) {
            uint32_t a[2][4], b[4][4];
            #pragma unroll
            for (int mt = 0; mt < 2; mt++) {
                const int r = wm * 32 + mt * 16 + row_a;
                ldsm4(a[mt][0], a[mt][1], a[mt][2], a[mt][3],
                      sA + sw_off(r, ks * 2 + ksel_a));
            }
            #pragma unroll
            for (int bt = 0; bt < 4; bt++) {
                const int n = wn * 64 + bt * 16 + row_b;
                ldsm4(b[bt][0], b[bt][1], b[bt][2], b[bt][3],
                      sB + sw_off(n, ks * 2 + ksel_b));
            }
            #pragma unroll
            for (int mt = 0; mt < 2; mt++)
                #pragma unroll
                for (int bt = 0; bt < 4; bt++) {
                    mma_f16(acc[mt][bt * 2],     a[mt], &b[bt][0]);
                    mma_f16(acc[mt][bt * 2 + 1], a[mt], &b[bt][2]);
                }
        }

        if (kt + 3 < ITERS) {
            const int sn = (kt + 3) & 3;
            load_stage(sbase + sn * STAGE_BYTES, sbase + sn * STAGE_BYTES + A_ST,
                       Ag, Wg, m0, n0, kt + 3, tid);
        }
        CP_COMMIT();
    }

    float2 bv[8];
    #pragma unroll
    for (int nf = 0; nf < 8; nf++) {
        const int n = n0 + wn * 64 + nf * 8 + (lane & 3) * 2;
        bv[nf] = *(const float2*)(bias + n);
    }
    #pragma unroll
    for (int mt = 0; mt < 2; mt++) {
        const int m = m0 + wm * 32 + mt * 16 + (lane >> 2);
        #pragma unroll
        for (int nf = 0; nf < 8; nf++) {
            const int n = n0 + wn * 64 + nf * 8 + (lane & 3) * 2;
            const __half2 o0 = __floats2half2_rn(acc[mt][nf][0] + bv[nf].x,
                                                 acc[mt][nf][1] + bv[nf].y);
            const __half2 o1 = __floats2half2_rn(acc[mt][nf][2] + bv[nf].x,
                                                 acc[mt][nf][3] + bv[nf].y);
            *(__half2*)&C[(size_t)m * N4 + n]       = o0;
            *(__half2*)&C[(size_t)(m + 8) * N4 + n] = o1;
        }
    }
}

// ---------------------------------------------------------------------------
// Fused LayerNorm + LSTM gates v2: two-pass with L1/L2 reload (low regs,
// higher occupancy). fp16 gate inputs, MUFU-approx transcendentals.
// ---------------------------------------------------------------------------
__device__ __forceinline__ float4 block_reduce_sum4(float4 v)
{
    __shared__ float4 sbuf[8];
    const int lane = threadIdx.x & 31;
    const int warp = threadIdx.x >> 5;
    #pragma unroll
    for (int o = 16; o > 0; o >>= 1) {
        v.x += __shfl_down_sync(0xffffffffu, v.x, o);
        v.y += __shfl_down_sync(0xffffffffu, v.y, o);
        v.z += __shfl_down_sync(0xffffffffu, v.z, o);
        v.w += __shfl_down_sync(0xffffffffu, v.w, o);
    }
    if (lane == 0) sbuf[warp] = v;
    __syncthreads();
    if (warp == 0) {
        v = (lane < 8) ? sbuf[lane] : make_float4(0.f, 0.f, 0.f, 0.f);
        #pragma unroll
        for (int o = 4; o > 0; o >>= 1) {
            v.x += __shfl_down_sync(0xffffffffu, v.x, o);
            v.y += __shfl_down_sync(0xffffffffu, v.y, o);
            v.z += __shfl_down_sync(0xffffffffu, v.z, o);
            v.w += __shfl_down_sync(0xffffffffu, v.w, o);
        }
        if (lane == 0) sbuf[0] = v;
    }
    __syncthreads();
    float4 res = sbuf[0];
    __syncthreads();
    return res;
}

__global__ void __launch_bounds__(256) ln_lstm_kernel(
    const float* __restrict__ c_prev,
    const float* __restrict__ g_i2h,  const float* __restrict__ be_i2h,
    const float* __restrict__ g_h2h,  const float* __restrict__ be_h2h,
    const float* __restrict__ g_c,    const float* __restrict__ be_c,
    float* __restrict__ out_h, float* __restrict__ out_c)
{
    const int row = blockIdx.x;
    const int t   = threadIdx.x;
    const __half2* gi = (const __half2*)g_gi + (size_t)row * (N4 / 2);
    const __half2* gh = (const __half2*)g_gh + (size_t)row * (N4 / 2);

    // Pass 1: statistics only (values dropped; rows stay L1/L2-resident)
    float4 s = make_float4(0.f, 0.f, 0.f, 0.f);
    #pragma unroll
    for (int k = 0; k < 8; k++) {
        const int h = k * 256 + t;
        const float2 a = __half22float2(gi[h]);
        const float2 b = __half22float2(gh[h]);
        s.x += a.x + a.y; s.y += a.x * a.x + a.y * a.y;
        s.z += b.x + b.y; s.w += b.x * b.x + b.y * b.y;
    }
    s = block_reduce_sum4(s);

    const float n1  = (float)N4;
    const float mi  = s.x / n1;
    const float mh  = s.z / n1;
    const float var_i = (s.y - n1 * mi * mi) * (1.0f / (n1 - 1.0f));
    const float var_h = (s.w - n1 * mh * mh) * (1.0f / (n1 - 1.0f));
    const float inv_i = fast_rcp(fast_sqrt(fmaxf(var_i, 0.f)) + 1e-6f);
    const float inv_h = fast_rcp(fast_sqrt(fmaxf(var_h, 0.f)) + 1e-6f);

    // Pass 2: reload gates (cache hits), compute normalized gate sums + cell
    float cn[2][2], og[2][2];
    float4 cs = make_float4(0.f, 0.f, 0.f, 0.f);
    #pragma unroll
    for (int kk = 0; kk < 2; kk++) {
        float sg[4][2];
        #pragma unroll
        for (int g = 0; g < 4; g++) {
            const int h = (g * 2 + kk) * 256 + t;
            const float2 a = __half22float2(gi[h]);
            const float2 b = __half22float2(gh[h]);
            const int pidx = g * 1024 + ((kk * 256 + t) << 1);
            const float2 ga = *(const float2*)(g_i2h + pidx);
            const float2 ba = *(const float2*)(be_i2h + pidx);
            const float2 gb = *(const float2*)(g_h2h + pidx);
            const float2 bb = *(const float2*)(be_h2h + pidx);
            sg[g][0] = ga.x * (a.x - mi) * inv_i + ba.x + gb.x * (b.x - mh) * inv_h + bb.x;
            sg[g][1] = ga.y * (a.y - mi) * inv_i + ba.y + gb.y * (b.y - mh) * inv_h + bb.y;
        }
        const int j = ((kk * 256 + t) << 1);
        const float2 cp = *(const float2*)(c_prev + (size_t)row * HDIM + j);
        const float cpv[2] = {cp.x, cp.y};
        #pragma unroll
        for (int x = 0; x < 2; x++) {
            cn[kk][x] = cpv[x] * fast_sigmoid(sg[1][x] + 1.0f)
                      + fast_tanh(sg[2][x]) * fast_sigmoid(sg[0][x]);
            og[kk][x] = sg[3][x];
            cs.x += cn[kk][x];
            cs.y += cn[kk][x] * cn[kk][x];
        }
    }
    cs = block_reduce_sum4(cs);

    const float n2   = (float)HDIM;
    const float mc   = cs.x / n2;
    const float var_c = (cs.y - n2 * mc * mc) * (1.0f / (n2 - 1.0f));
    const float inv_c = fast_rcp(fast_sqrt(fmaxf(var_c, 0.f)) + 1e-6f);

    #pragma unroll
    for (int kk = 0; kk < 2; kk++) {
        const int j = ((kk * 256 + t) << 1);
        const float2 gcv  = *(const float2*)(g_c + j);
        const float2 becv = *(const float2*)(be_c + j);
        float2 oc, oh;
        oc.x = gcv.x * (cn[kk][0] - mc) * inv_c + becv.x;
        oc.y = gcv.y * (cn[kk][1] - mc) * inv_c + becv.y;
        oh.x = fast_sigmoid(og[kk][0]) * fast_tanh(oc.x);
        oh.y = fast_sigmoid(og[kk][1]) * fast_tanh(oc.y);
        *(float2*)(out_c + (size_t)row * HDIM + j) = oc;
        *(float2*)(out_h + (size_t)row * HDIM + j) = oh;
    }
}

// ---------------------------------------------------------------------------
extern "C" void kernel_launch(void* const* d_in, const int* in_sizes, int n_in,
                              void* d_out, int out_size)
{
    const float* input  = (const float*)d_in[0];
    const float* h_prev = (const float*)d_in[1];
    const float* c_prev = (const float*)d_in[2];
    const float* w_i2h  = (const float*)d_in[3];
    const float* b_i2h  = (const float*)d_in[4];
    const float* w_h2h  = (const float*)d_in[5];
    const float* b_h2h  = (const float*)d_in[6];
    const float* gi2h   = (const float*)d_in[7];
    const float* bei2h  = (const float*)d_in[8];
    const float* gh2h   = (const float*)d_in[9];
    const float* beh2h  = (const float*)d_in[10];
    const float* gc     = (const float*)d_in[11];
    const float* bec    = (const float*)d_in[12];

    float* out_h = (float*)d_out;
    float* out_c = (float*)d_out + (size_t)BSZ * HDIM;

    // conversions
    cast_act_kernel<<<dim3(BSZ * KDIM / (256 * 4), 1, 2), 256>>>(input, h_prev);
    cast_wt_kernel<<<dim3(N4 / 32, KDIM / 32, 2), 128>>>(w_i2h, w_h2h);

    // GEMMs on tensor pipe (mma.sync fp16, K=1024, 512 threads, 4 stages)
    cudaFuncSetAttribute(gemm_mma_kernel,
                         cudaFuncAttributeMaxDynamicSharedMemorySize, GEMM_SMEM);
    gemm_mma_kernel<<<dim3(N4 / BN, BSZ / BM, 2), 512, GEMM_SMEM>>>(b_i2h, b_h2h);

    ln_lstm_kernel<<<BSZ, 256>>>(c_prev, gi2h, bei2h, gh2h, beh2h, gc, bec,
                                 out_h, out_c);
}